// round 12
// baseline (speedup 1.0000x reference)
#include <cuda_runtime.h>
#include <cuda_bf16.h>
#include <cstdint>

#define N_NODES 100000
#define N_EDGES 1600000
#define F 128
#define SCAN_B 196      // ceil(100001 / 512)
#define TM 64
#define GEMM_BLOCKS ((N_NODES + TM - 1) / TM)   // 1563
#define N_PAD (GEMM_BLOCKS * TM)                // 100032 (tail rows stay zero)

// ---------------- scratch (static device globals; no cudaMalloc) ------------
__device__ __align__(16) int g_cnt[N_NODES + 1];   // zero-init; scan re-zeroes
__device__ __align__(16) int g_off[N_NODES + 1];
__device__ __align__(16) int g_cur[N_NODES];
__device__ __align__(16) int g_csr[N_EDGES];
__device__ __align__(16) unsigned long long g_desc[SCAN_B];  // lookback state
// agg output, pre-split bf16 hi/lo, pre-swizzled in GEMM smem layout
__device__ __align__(16) unsigned g_thi[(size_t)N_PAD * 64];
__device__ __align__(16) unsigned g_tlo[(size_t)N_PAD * 64];
__device__ __align__(16) float g_m[(size_t)N_NODES * F]; // relu(H) out (fp32)
__device__ __align__(16) float g_wc[2][F * F];           // W12@W21, W22@W31 (fp32)
__device__ __align__(16) float g_bc[2][F];               // b12@W21, b22@W31
// pre-split, transposed (Wt[n][k]), XOR-swizzled weights: [slot][hi/lo][128*128]
__device__ __align__(16) __nv_bfloat16 g_wp[3][2][F * F];

// ---------------- helpers -------------------------------------------------------
__device__ __forceinline__ unsigned pkbf2(float lo, float hi) {
    unsigned r;
    asm("cvt.rn.bf16x2.f32 %0, %1, %2;" : "=r"(r) : "f"(hi), "f"(lo));
    return r;
}
__device__ __forceinline__ unsigned s2u(const void* p) {
    unsigned a;
    asm("{ .reg .u64 t; cvta.to.shared.u64 t, %1; cvt.u32.u64 %0, t; }"
        : "=r"(a) : "l"(p));
    return a;
}
__device__ __forceinline__ void cp16(unsigned smem_addr, const void* gptr) {
    asm volatile("cp.async.cg.shared.global [%0], [%1], 16;" ::
                 "r"(smem_addr), "l"(gptr));
}
__device__ __forceinline__ void cp_commit() { asm volatile("cp.async.commit_group;"); }
__device__ __forceinline__ void cp_wait0()  { asm volatile("cp.async.wait_group 0;"); }

__device__ __forceinline__ void mma16816(float* d, const unsigned* a,
                                         const unsigned* b) {
    asm("mma.sync.aligned.m16n8k16.row.col.f32.bf16.bf16.f32 "
        "{%0,%1,%2,%3}, {%4,%5,%6,%7}, {%8,%9}, {%0,%1,%2,%3};"
        : "+f"(d[0]), "+f"(d[1]), "+f"(d[2]), "+f"(d[3])
        : "r"(a[0]), "r"(a[1]), "r"(a[2]), "r"(a[3]), "r"(b[0]), "r"(b[1]));
}

// swizzled 32-bit word index within a 128-col bf16 row (64 words/row)
__device__ __forceinline__ int swz(int row, int w) {
    return row * 64 + (w ^ ((row & 7) << 2));
}

// ---------------- edge dtype: block-local detection ---------------------------
__device__ __forceinline__ int block_is64(const void* ei, int e) {
    unsigned hw = ((const unsigned*)ei)[2 * e + 1];
    int any = __syncthreads_or(hw != 0u);
    return any ? 0 : 1;
}

// ---------------- CSR build ----------------------------------------------------
__global__ void k_count(const void* __restrict__ ei) {
    if (blockIdx.x == 0 && threadIdx.x < SCAN_B) g_desc[threadIdx.x] = 0ULL;
    int e = blockIdx.x * 256 + threadIdx.x;
    int is64 = block_is64(ei, e);
    int d = is64 ? (int)(((const long long*)ei)[N_EDGES + e])
                 : ((const int*)ei)[N_EDGES + e];
    atomicAdd(&g_cnt[d + 1], 1);
}

// single-kernel decoupled-lookback scan over g_cnt[0..N_NODES] -> g_off, g_cur
__global__ void k_scan_lb() {
    __shared__ int wsum[16];
    __shared__ int s_exc;
    int tid = threadIdx.x, b = blockIdx.x;
    int i = b * 512 + tid;
    int lane = tid & 31, w = tid >> 5;
    int v = (i <= N_NODES) ? g_cnt[i] : 0;
    if (i <= N_NODES) g_cnt[i] = 0;                   // restore invariant
    int s = v;
    #pragma unroll
    for (int o = 1; o < 32; o <<= 1) {
        int t = __shfl_up_sync(0xffffffffu, s, o);
        if (lane >= o) s += t;
    }
    if (lane == 31) wsum[w] = s;
    __syncthreads();
    if (w == 0) {
        int ws = (lane < 16) ? wsum[lane] : 0;
        #pragma unroll
        for (int o = 1; o < 16; o <<= 1) {
            int t = __shfl_up_sync(0xffffffffu, ws, o);
            if (lane >= o) ws += t;
        }
        if (lane < 16) wsum[lane] = ws;
    }
    __syncthreads();
    int incl = s + (w > 0 ? wsum[w - 1] : 0);
    int total = wsum[15];
    if (tid == 0) {
        unsigned long long pub =
            ((unsigned long long)(b == 0 ? 2u : 1u) << 32) | (unsigned)total;
        atomicExch(&g_desc[b], pub);
    }
    int exc = 0;
    if (b > 0) {
        if (tid == 0) {
            int p = b - 1, run = 0;
            while (true) {
                unsigned long long d = atomicAdd(&g_desc[p], 0ULL);
                unsigned f = (unsigned)(d >> 32);
                if (f == 0u) continue;
                run += (int)(d & 0xffffffffu);
                if (f == 2u) break;
                p--;
            }
            s_exc = run;
            atomicExch(&g_desc[b], (2ULL << 32) | (unsigned)(run + total));
        }
        __syncthreads();
        exc = s_exc;
    }
    if (i <= N_NODES) {
        int val = exc + incl;
        g_off[i] = val;
        if (i < N_NODES) g_cur[i] = val;
    }
}

__global__ void k_fill(const void* __restrict__ ei) {
    int e = blockIdx.x * 256 + threadIdx.x;
    int is64 = block_is64(ei, e);
    int s, d;
    if (is64) {
        s = (int)(((const long long*)ei)[e]);
        d = (int)(((const long long*)ei)[N_EDGES + e]);
    } else {
        s = ((const int*)ei)[e];
        d = ((const int*)ei)[N_EDGES + e];
    }
    int p = atomicAdd(&g_cur[d], 1);
    g_csr[p] = s;
}

// ---------------- aggregation + split: g_thi/g_tlo[i] = split(in[i]+sum nbrs) ---
// Output layout matches GEMM smem exactly: row node, word (2l)^((node&7)<<2).
__global__ void k_agg(const float* __restrict__ x, int layer) {
    const float* in = (layer == 0) ? x : (const float*)g_m;
    int w = (blockIdx.x * blockDim.x + threadIdx.x) >> 5;
    if (w >= N_NODES) return;
    int lane = threadIdx.x & 31;
    const float4* xin = (const float4*)in;
    float4 acc = xin[(size_t)w * 32 + lane];
    int e = g_off[w];
    int end = g_off[w + 1];
    for (; e + 4 <= end; e += 4) {
        int s0 = g_csr[e], s1 = g_csr[e + 1], s2 = g_csr[e + 2], s3 = g_csr[e + 3];
        float4 v0 = xin[(size_t)s0 * 32 + lane];
        float4 v1 = xin[(size_t)s1 * 32 + lane];
        float4 v2 = xin[(size_t)s2 * 32 + lane];
        float4 v3 = xin[(size_t)s3 * 32 + lane];
        acc.x += (v0.x + v1.x) + (v2.x + v3.x);
        acc.y += (v0.y + v1.y) + (v2.y + v3.y);
        acc.z += (v0.z + v1.z) + (v2.z + v3.z);
        acc.w += (v0.w + v1.w) + (v2.w + v3.w);
    }
    for (; e < end; e++) {
        int s0 = g_csr[e];
        float4 v0 = xin[(size_t)s0 * 32 + lane];
        acc.x += v0.x; acc.y += v0.y; acc.z += v0.z; acc.w += v0.w;
    }
    // split to bf16 hi/lo and store pre-swizzled
    __nv_bfloat16 bx = __float2bfloat16(acc.x);
    __nv_bfloat16 by = __float2bfloat16(acc.y);
    __nv_bfloat16 bz = __float2bfloat16(acc.z);
    __nv_bfloat16 bw = __float2bfloat16(acc.w);
    uint2 HI, LO;
    HI.x = ((unsigned)__bfloat16_as_ushort(by) << 16) | __bfloat16_as_ushort(bx);
    HI.y = ((unsigned)__bfloat16_as_ushort(bw) << 16) | __bfloat16_as_ushort(bz);
    LO.x = pkbf2(acc.x - __bfloat162float(bx), acc.y - __bfloat162float(by));
    LO.y = pkbf2(acc.z - __bfloat162float(bz), acc.w - __bfloat162float(bw));
    int wordp = (2 * lane) ^ ((w & 7) << 2);
    *(uint2*)(g_thi + (size_t)w * 64 + wordp) = HI;
    *(uint2*)(g_tlo + (size_t)w * 64 + wordp) = LO;
}

// ---------------- combined weights: Wc = A@B (fp32), bc = bA@B ------------------
// 16 blocks: prod = b>>3, row group = b&7 (16 rows each). ~10 us.
__global__ void k_wcombine(const float* __restrict__ w12, const float* __restrict__ b12,
                           const float* __restrict__ w21, const float* __restrict__ w22,
                           const float* __restrict__ b22, const float* __restrict__ w31) {
    int prod = blockIdx.x >> 3, rowg = blockIdx.x & 7;
    const float* A  = prod ? w22 : w12;
    const float* bA = prod ? b22 : b12;
    const float* B  = prod ? w31 : w21;
    float* C  = g_wc[prod];
    float* bc = g_bc[prod];
    for (int idx = threadIdx.x; idx < 16 * F; idx += blockDim.x) {
        int k = rowg * 16 + (idx >> 7);
        int j = idx & 127;
        float s = 0.f;
        #pragma unroll 4
        for (int m = 0; m < F; m++) s += A[k * F + m] * B[m * F + j];
        C[k * F + j] = s;
    }
    if (rowg == 0 && threadIdx.x < F) {
        int j = threadIdx.x;
        float s = 0.f;
        #pragma unroll 4
        for (int m = 0; m < F; m++) s += bA[m] * B[m * F + j];
        bc[j] = s;
    }
}

// ---------------- weight prep: W[k][j] -> Wt_hi/lo[n=j][k], swizzled (split only)
__global__ void k_wprep(const float* __restrict__ w11) {
    const float* W = (blockIdx.x == 0) ? w11 : g_wc[blockIdx.x - 1];
    __nv_bfloat16* dhi = &g_wp[blockIdx.x][0][0];
    __nv_bfloat16* dlo = &g_wp[blockIdx.x][1][0];
    for (int idx = threadIdx.x; idx < F * F; idx += blockDim.x) {
        int n = idx >> 7, k = idx & 127;
        float v = W[k * F + n];
        __nv_bfloat16 h = __float2bfloat16(v);
        float l = v - __bfloat162float(h);
        int e = swz(n, k >> 1) * 2 + (k & 1);
        dhi[e] = h;
        dlo[e] = __float2bfloat16(l);
    }
}

// ---------------- tensor-core GEMM: H = relu(t @ W + bias), tile 64x128 ---------
// Warp tiling: warp (r = wid&1, c = wid>>1) computes rows r*32..+31 (2 strips)
// and cols c*64..+63 (8 n-tiles). Each B fragment feeds 2 m-strips (2x reuse).
// bias[col] = bias1[col] + (1+deg_row)*g_bc[bc_sel-1][col]  (bc_sel=0: none)
// dot_mode: outS[n] = H[n,:].w32 + b32 ; else g_m[n,:] = H[n,:]
#define SM_TOT (2 * TM * F * 2 + 2 * F * F * 2 + 3 * F * 4 + TM * 4)
__global__ void __launch_bounds__(128, 2)
k_gemm_mma(int slot, const float* __restrict__ bias1, int bc_sel, int dot_mode,
           const float* __restrict__ w32, const float* __restrict__ b32,
           float* __restrict__ outS) {
    extern __shared__ __align__(16) char smem[];
    __nv_bfloat16* sAhi = (__nv_bfloat16*)smem;            // 16 KB
    __nv_bfloat16* sAlo = sAhi + TM * F;                   // 16 KB
    __nv_bfloat16* sBhi = sAlo + TM * F;                   // 64 KB (hi then lo)
    float* sBias1 = (float*)(sBhi + 2 * F * F);
    float* sBiasC = sBias1 + F;
    float* sW32   = sBiasC + F;
    float* sRow   = sW32 + F;                              // TM floats (dot mode)

    float* out = (float*)g_m;

    int tid = threadIdx.x;
    int lane = tid & 31, wid = tid >> 5;
    int nbase = blockIdx.x * TM;

    // ---- B (Wt hi+lo, pre-swizzled): linear 64 KB cp.async ----
    unsigned sB = s2u(sBhi);
    const char* gb = (const char*)&g_wp[slot][0][0];
    #pragma unroll
    for (int i = 0; i < 32; i++)
        cp16(sB + (tid + i * 128) * 16, gb + (size_t)(tid + i * 128) * 16);
    // ---- A (pre-split, pre-swizzled): linear 2 x 16 KB cp.async ----
    unsigned sAh = s2u(sAhi);
    unsigned sAl = s2u(sAlo);
    const char* gah = (const char*)(g_thi + (size_t)nbase * 64);
    const char* gal = (const char*)(g_tlo + (size_t)nbase * 64);
    #pragma unroll
    for (int i = 0; i < 8; i++) {
        cp16(sAh + (tid + i * 128) * 16, gah + (size_t)(tid + i * 128) * 16);
        cp16(sAl + (tid + i * 128) * 16, gal + (size_t)(tid + i * 128) * 16);
    }
    cp_commit();
    if (tid < F) {
        sBias1[tid] = bias1[tid];
        sBiasC[tid] = bc_sel ? g_bc[bc_sel - 1][tid] : 0.f;
        sW32[tid]   = dot_mode ? w32[tid] : 0.f;
        if (tid < TM) sRow[tid] = 0.f;
    }
    cp_wait0();
    __syncthreads();

    const unsigned* uAhi = (const unsigned*)sAhi;
    const unsigned* uAlo = (const unsigned*)sAlo;
    const unsigned* uBhi = (const unsigned*)sBhi;
    const unsigned* uBlo = uBhi + F * F / 2;

    float acc[2][8][4];
    #pragma unroll
    for (int st = 0; st < 2; st++)
        #pragma unroll
        for (int i = 0; i < 8; i++)
            #pragma unroll
            for (int j = 0; j < 4; j++) acc[st][i][j] = 0.f;

    int g = lane >> 2;            // group id 0..7
    int t = lane & 3;             // thread in group
    int rowbase = (wid & 1) * 32; // 0 or 32
    int colbase = (wid >> 1) * 64;// 0 or 64
    int m0 = rowbase + g;         // strip 0 lower row
    int m1 = rowbase + 16 + g;    // strip 1 lower row

    #pragma unroll
    for (int s = 0; s < 8; s++) {
        int w0 = 8 * s + t, w1 = w0 + 4;
        unsigned a0h[4], a0l[4], a1h[4], a1l[4];
        a0h[0] = uAhi[swz(m0, w0)];     a0h[1] = uAhi[swz(m0 + 8, w0)];
        a0h[2] = uAhi[swz(m0, w1)];     a0h[3] = uAhi[swz(m0 + 8, w1)];
        a0l[0] = uAlo[swz(m0, w0)];     a0l[1] = uAlo[swz(m0 + 8, w0)];
        a0l[2] = uAlo[swz(m0, w1)];     a0l[3] = uAlo[swz(m0 + 8, w1)];
        a1h[0] = uAhi[swz(m1, w0)];     a1h[1] = uAhi[swz(m1 + 8, w0)];
        a1h[2] = uAhi[swz(m1, w1)];     a1h[3] = uAhi[swz(m1 + 8, w1)];
        a1l[0] = uAlo[swz(m1, w0)];     a1l[1] = uAlo[swz(m1 + 8, w0)];
        a1l[2] = uAlo[swz(m1, w1)];     a1l[3] = uAlo[swz(m1 + 8, w1)];
        #pragma unroll
        for (int nt = 0; nt < 8; nt++) {
            int n0 = colbase + nt * 8 + g;
            unsigned bh[2], bl[2];
            bh[0] = uBhi[swz(n0, w0)];  bh[1] = uBhi[swz(n0, w1)];
            bl[0] = uBlo[swz(n0, w0)];  bl[1] = uBlo[swz(n0, w1)];
            mma16816(acc[0][nt], a0h, bh);
            mma16816(acc[0][nt], a0h, bl);
            mma16816(acc[0][nt], a0l, bh);
            mma16816(acc[1][nt], a1h, bh);
            mma16816(acc[1][nt], a1h, bl);
            mma16816(acc[1][nt], a1l, bh);
        }
    }

    // ---- epilogue ----
    if (!dot_mode) {
        #pragma unroll
        for (int st = 0; st < 2; st++) {
            int m = rowbase + st * 16 + g;
            int node0 = nbase + m;
            int node1 = node0 + 8;
            float sc0 = 0.f, sc1 = 0.f;
            if (bc_sel) {
                if (node0 < N_NODES)
                    sc0 = 1.f + (float)(g_off[node0 + 1] - g_off[node0]);
                if (node1 < N_NODES)
                    sc1 = 1.f + (float)(g_off[node1 + 1] - g_off[node1]);
            }
            #pragma unroll
            for (int nt = 0; nt < 8; nt++) {
                int col = colbase + nt * 8 + 2 * t;
                float bx = sBias1[col], by = sBias1[col + 1];
                float cx = sBiasC[col], cy = sBiasC[col + 1];
                float2 o0, o1;
                o0.x = fmaxf(acc[st][nt][0] + bx + sc0 * cx, 0.f);
                o0.y = fmaxf(acc[st][nt][1] + by + sc0 * cy, 0.f);
                o1.x = fmaxf(acc[st][nt][2] + bx + sc1 * cx, 0.f);
                o1.y = fmaxf(acc[st][nt][3] + by + sc1 * cy, 0.f);
                if (node0 < N_NODES) *(float2*)(out + (size_t)node0 * F + col) = o0;
                if (node1 < N_NODES) *(float2*)(out + (size_t)node1 * F + col) = o1;
            }
        }
    } else {
        #pragma unroll
        for (int st = 0; st < 2; st++) {
            int m = rowbase + st * 16 + g;
            int node0 = nbase + m;
            int node1 = node0 + 8;
            float sc0 = 0.f, sc1 = 0.f;
            if (bc_sel) {
                if (node0 < N_NODES)
                    sc0 = 1.f + (float)(g_off[node0 + 1] - g_off[node0]);
                if (node1 < N_NODES)
                    sc1 = 1.f + (float)(g_off[node1 + 1] - g_off[node1]);
            }
            float p0 = 0.f, p1 = 0.f;
            #pragma unroll
            for (int nt = 0; nt < 8; nt++) {
                int col = colbase + nt * 8 + 2 * t;
                float bx = sBias1[col], by = sBias1[col + 1];
                float cx = sBiasC[col], cy = sBiasC[col + 1];
                p0 += fmaxf(acc[st][nt][0] + bx + sc0 * cx, 0.f) * sW32[col]
                    + fmaxf(acc[st][nt][1] + by + sc0 * cy, 0.f) * sW32[col + 1];
                p1 += fmaxf(acc[st][nt][2] + bx + sc1 * cx, 0.f) * sW32[col]
                    + fmaxf(acc[st][nt][3] + by + sc1 * cy, 0.f) * sW32[col + 1];
            }
            p0 += __shfl_xor_sync(0xffffffffu, p0, 1);
            p0 += __shfl_xor_sync(0xffffffffu, p0, 2);
            p1 += __shfl_xor_sync(0xffffffffu, p1, 1);
            p1 += __shfl_xor_sync(0xffffffffu, p1, 2);
            if (t == 0) {
                atomicAdd(&sRow[m], p0);        // two col-half warps accumulate
                atomicAdd(&sRow[m + 8], p1);
            }
        }
        __syncthreads();
        if (tid < TM) {
            int node = nbase + tid;
            if (node < N_NODES) outS[node] = sRow[tid] + b32[0];
        }
    }
}

// ---------------- launch ---------------------------------------------------------
extern "C" void kernel_launch(void* const* d_in, const int* in_sizes, int n_in,
                              void* d_out, int out_size) {
    const float* x = (const float*)d_in[0];
    const void* ei = d_in[1];
    const float* w11 = (const float*)d_in[2];
    const float* b11 = (const float*)d_in[3];
    const float* w12 = (const float*)d_in[4];
    const float* b12 = (const float*)d_in[5];
    const float* w21 = (const float*)d_in[6];
    const float* b21 = (const float*)d_in[7];
    const float* w22 = (const float*)d_in[8];
    const float* b22 = (const float*)d_in[9];
    const float* w31 = (const float*)d_in[10];
    const float* b31 = (const float*)d_in[11];
    const float* w32 = (const float*)d_in[12];
    const float* b32 = (const float*)d_in[13];
    float* out = (float*)d_out;

    static int smem_set = 0;
    if (!smem_set) {
        cudaFuncSetAttribute(k_gemm_mma, cudaFuncAttributeMaxDynamicSharedMemorySize,
                             SM_TOT);
        smem_set = 1;
    }

    const int AGG_BLOCKS = (N_NODES * 32 + 255) / 256;   // warp per node

    k_count<<<N_EDGES / 256, 256>>>(ei);      // 1 (also zeroes lookback state)
    k_scan_lb<<<SCAN_B, 512>>>();             // 2
    k_fill<<<N_EDGES / 256, 256>>>(ei);       // 3
    k_agg<<<AGG_BLOCKS, 256>>>(x, 0);         // 4
    k_wcombine<<<16, 256>>>(w12, b12, w21, w22, b22, w31);  // 5
    k_wprep<<<3, 256>>>(w11);                 // 6

    // H1 = relu(agg(x)@W11 + b11)
    k_gemm_mma<<<GEMM_BLOCKS, 128, SM_TOT>>>(0, b11, 0, 0, w32, b32, out);
    // H2 = relu(agg(H1)@Wc2 + (1+deg)bc2 + b21)
    k_agg<<<AGG_BLOCKS, 256>>>(x, 1);
    k_gemm_mma<<<GEMM_BLOCKS, 128, SM_TOT>>>(1, b21, 1, 0, w32, b32, out);
    // out = relu(agg(H2)@Wc3 + (1+deg)bc3 + b31) . w32 + b32
    k_agg<<<AGG_BLOCKS, 256>>>(x, 2);
    k_gemm_mma<<<GEMM_BLOCKS, 128, SM_TOT>>>(2, b31, 2, 1, w32, b32, out);
}

// round 13
// speedup vs baseline: 1.0582x; 1.0582x over previous
#include <cuda_runtime.h>
#include <cuda_bf16.h>
#include <cuda_fp16.h>
#include <cstdint>

#define N_NODES 100000
#define N_EDGES 1600000
#define F 128
#define SCAN_B 196      // ceil(100001 / 512)
#define TM 64
#define GEMM_BLOCKS ((N_NODES + TM - 1) / TM)   // 1563
#define N_PAD (GEMM_BLOCKS * TM)                // 100032 (tail rows stay zero)

// ---------------- scratch (static device globals; no cudaMalloc) ------------
__device__ __align__(16) int g_cnt[N_NODES + 1];   // zero-init; scan re-zeroes
__device__ __align__(16) int g_off[N_NODES + 1];
__device__ __align__(16) int g_cur[N_NODES];
__device__ __align__(16) int g_csr[N_EDGES];
__device__ __align__(16) unsigned long long g_desc[SCAN_B];  // lookback state
// agg output, pre-split bf16 hi/lo, pre-swizzled in GEMM smem layout
__device__ __align__(16) unsigned g_thi[(size_t)N_PAD * 64];
__device__ __align__(16) unsigned g_tlo[(size_t)N_PAD * 64];
__device__ __align__(16) __half g_m[(size_t)N_NODES * F]; // relu(H), fp16
__device__ __align__(16) float g_wc[2][F * F];           // W12@W21, W22@W31 (fp32)
__device__ __align__(16) float g_bc[2][F];               // b12@W21, b22@W31
// pre-split, transposed (Wt[n][k]), XOR-swizzled weights: [slot][hi/lo][128*128]
__device__ __align__(16) __nv_bfloat16 g_wp[3][2][F * F];

// ---------------- helpers -------------------------------------------------------
__device__ __forceinline__ unsigned pkbf2(float lo, float hi) {
    unsigned r;
    asm("cvt.rn.bf16x2.f32 %0, %1, %2;" : "=r"(r) : "f"(hi), "f"(lo));
    return r;
}
__device__ __forceinline__ unsigned s2u(const void* p) {
    unsigned a;
    asm("{ .reg .u64 t; cvta.to.shared.u64 t, %1; cvt.u32.u64 %0, t; }"
        : "=r"(a) : "l"(p));
    return a;
}
__device__ __forceinline__ void cp16(unsigned smem_addr, const void* gptr) {
    asm volatile("cp.async.cg.shared.global [%0], [%1], 16;" ::
                 "r"(smem_addr), "l"(gptr));
}
__device__ __forceinline__ void cp_commit() { asm volatile("cp.async.commit_group;"); }
__device__ __forceinline__ void cp_wait0()  { asm volatile("cp.async.wait_group 0;"); }

__device__ __forceinline__ void mma16816(float* d, const unsigned* a,
                                         const unsigned* b) {
    asm("mma.sync.aligned.m16n8k16.row.col.f32.bf16.bf16.f32 "
        "{%0,%1,%2,%3}, {%4,%5,%6,%7}, {%8,%9}, {%0,%1,%2,%3};"
        : "+f"(d[0]), "+f"(d[1]), "+f"(d[2]), "+f"(d[3])
        : "r"(a[0]), "r"(a[1]), "r"(a[2]), "r"(a[3]), "r"(b[0]), "r"(b[1]));
}

// swizzled 32-bit word index within a 128-col bf16 row (64 words/row)
__device__ __forceinline__ int swz(int row, int w) {
    return row * 64 + (w ^ ((row & 7) << 2));
}

__device__ __forceinline__ float4 up4(uint2 u) {
    __half2 a = *(__half2*)&u.x, b = *(__half2*)&u.y;
    float2 fa = __half22float2(a), fb = __half22float2(b);
    return make_float4(fa.x, fa.y, fb.x, fb.y);
}

// ---------------- edge dtype: block-local detection ---------------------------
__device__ __forceinline__ int block_is64(const void* ei, int e) {
    unsigned hw = ((const unsigned*)ei)[2 * e + 1];
    int any = __syncthreads_or(hw != 0u);
    return any ? 0 : 1;
}

// ---------------- CSR build ----------------------------------------------------
__global__ void k_count(const void* __restrict__ ei) {
    if (blockIdx.x == 0 && threadIdx.x < SCAN_B) g_desc[threadIdx.x] = 0ULL;
    int e = blockIdx.x * 256 + threadIdx.x;
    int is64 = block_is64(ei, e);
    int d = is64 ? (int)(((const long long*)ei)[N_EDGES + e])
                 : ((const int*)ei)[N_EDGES + e];
    atomicAdd(&g_cnt[d + 1], 1);
}

// single-kernel decoupled-lookback scan over g_cnt[0..N_NODES] -> g_off, g_cur
__global__ void k_scan_lb() {
    __shared__ int wsum[16];
    __shared__ int s_exc;
    int tid = threadIdx.x, b = blockIdx.x;
    int i = b * 512 + tid;
    int lane = tid & 31, w = tid >> 5;
    int v = (i <= N_NODES) ? g_cnt[i] : 0;
    if (i <= N_NODES) g_cnt[i] = 0;                   // restore invariant
    int s = v;
    #pragma unroll
    for (int o = 1; o < 32; o <<= 1) {
        int t = __shfl_up_sync(0xffffffffu, s, o);
        if (lane >= o) s += t;
    }
    if (lane == 31) wsum[w] = s;
    __syncthreads();
    if (w == 0) {
        int ws = (lane < 16) ? wsum[lane] : 0;
        #pragma unroll
        for (int o = 1; o < 16; o <<= 1) {
            int t = __shfl_up_sync(0xffffffffu, ws, o);
            if (lane >= o) ws += t;
        }
        if (lane < 16) wsum[lane] = ws;
    }
    __syncthreads();
    int incl = s + (w > 0 ? wsum[w - 1] : 0);
    int total = wsum[15];
    if (tid == 0) {
        unsigned long long pub =
            ((unsigned long long)(b == 0 ? 2u : 1u) << 32) | (unsigned)total;
        atomicExch(&g_desc[b], pub);
    }
    int exc = 0;
    if (b > 0) {
        if (tid == 0) {
            int p = b - 1, run = 0;
            while (true) {
                unsigned long long d = atomicAdd(&g_desc[p], 0ULL);
                unsigned f = (unsigned)(d >> 32);
                if (f == 0u) continue;
                run += (int)(d & 0xffffffffu);
                if (f == 2u) break;
                p--;
            }
            s_exc = run;
            atomicExch(&g_desc[b], (2ULL << 32) | (unsigned)(run + total));
        }
        __syncthreads();
        exc = s_exc;
    }
    if (i <= N_NODES) {
        int val = exc + incl;
        g_off[i] = val;
        if (i < N_NODES) g_cur[i] = val;
    }
}

__global__ void k_fill(const void* __restrict__ ei) {
    int e = blockIdx.x * 256 + threadIdx.x;
    int is64 = block_is64(ei, e);
    int s, d;
    if (is64) {
        s = (int)(((const long long*)ei)[e]);
        d = (int)(((const long long*)ei)[N_EDGES + e]);
    } else {
        s = ((const int*)ei)[e];
        d = ((const int*)ei)[N_EDGES + e];
    }
    int p = atomicAdd(&g_cur[d], 1);
    g_csr[p] = s;
}

// ---------------- aggregation + split: t = in[i] + sum nbrs; store bf16 hi/lo ---
// layer 0: input x fp32; layers 1,2: input g_m fp16 (half the gather bytes).
// Output layout matches GEMM smem exactly: row node, word (2l)^((node&7)<<2).
__global__ void k_agg(const float* __restrict__ x, int layer) {
    int w = (blockIdx.x * blockDim.x + threadIdx.x) >> 5;
    if (w >= N_NODES) return;
    int lane = threadIdx.x & 31;
    float4 acc;
    int e = g_off[w];
    int end = g_off[w + 1];
    if (layer == 0) {
        const float4* xin = (const float4*)x;
        acc = xin[(size_t)w * 32 + lane];
        for (; e + 4 <= end; e += 4) {
            int s0 = g_csr[e], s1 = g_csr[e + 1], s2 = g_csr[e + 2], s3 = g_csr[e + 3];
            float4 v0 = xin[(size_t)s0 * 32 + lane];
            float4 v1 = xin[(size_t)s1 * 32 + lane];
            float4 v2 = xin[(size_t)s2 * 32 + lane];
            float4 v3 = xin[(size_t)s3 * 32 + lane];
            acc.x += (v0.x + v1.x) + (v2.x + v3.x);
            acc.y += (v0.y + v1.y) + (v2.y + v3.y);
            acc.z += (v0.z + v1.z) + (v2.z + v3.z);
            acc.w += (v0.w + v1.w) + (v2.w + v3.w);
        }
        for (; e < end; e++) {
            int s0 = g_csr[e];
            float4 v0 = xin[(size_t)s0 * 32 + lane];
            acc.x += v0.x; acc.y += v0.y; acc.z += v0.z; acc.w += v0.w;
        }
    } else {
        const uint2* hin = (const uint2*)g_m;   // 4 halves per uint2, 32/row
        acc = up4(hin[(size_t)w * 32 + lane]);
        for (; e + 4 <= end; e += 4) {
            int s0 = g_csr[e], s1 = g_csr[e + 1], s2 = g_csr[e + 2], s3 = g_csr[e + 3];
            float4 v0 = up4(hin[(size_t)s0 * 32 + lane]);
            float4 v1 = up4(hin[(size_t)s1 * 32 + lane]);
            float4 v2 = up4(hin[(size_t)s2 * 32 + lane]);
            float4 v3 = up4(hin[(size_t)s3 * 32 + lane]);
            acc.x += (v0.x + v1.x) + (v2.x + v3.x);
            acc.y += (v0.y + v1.y) + (v2.y + v3.y);
            acc.z += (v0.z + v1.z) + (v2.z + v3.z);
            acc.w += (v0.w + v1.w) + (v2.w + v3.w);
        }
        for (; e < end; e++) {
            int s0 = g_csr[e];
            float4 v0 = up4(hin[(size_t)s0 * 32 + lane]);
            acc.x += v0.x; acc.y += v0.y; acc.z += v0.z; acc.w += v0.w;
        }
    }
    // split to bf16 hi/lo and store pre-swizzled
    __nv_bfloat16 bx = __float2bfloat16(acc.x);
    __nv_bfloat16 by = __float2bfloat16(acc.y);
    __nv_bfloat16 bz = __float2bfloat16(acc.z);
    __nv_bfloat16 bw = __float2bfloat16(acc.w);
    uint2 HI, LO;
    HI.x = ((unsigned)__bfloat16_as_ushort(by) << 16) | __bfloat16_as_ushort(bx);
    HI.y = ((unsigned)__bfloat16_as_ushort(bw) << 16) | __bfloat16_as_ushort(bz);
    LO.x = pkbf2(acc.x - __bfloat162float(bx), acc.y - __bfloat162float(by));
    LO.y = pkbf2(acc.z - __bfloat162float(bz), acc.w - __bfloat162float(bw));
    int wordp = (2 * lane) ^ ((w & 7) << 2);
    *(uint2*)(g_thi + (size_t)w * 64 + wordp) = HI;
    *(uint2*)(g_tlo + (size_t)w * 64 + wordp) = LO;
}

// ---------------- combined weights: Wc = A@B (fp32), bc = bA@B ------------------
// 16 blocks: prod = b>>3, row group = b&7 (16 rows each). ~10 us.
__global__ void k_wcombine(const float* __restrict__ w12, const float* __restrict__ b12,
                           const float* __restrict__ w21, const float* __restrict__ w22,
                           const float* __restrict__ b22, const float* __restrict__ w31) {
    int prod = blockIdx.x >> 3, rowg = blockIdx.x & 7;
    const float* A  = prod ? w22 : w12;
    const float* bA = prod ? b22 : b12;
    const float* B  = prod ? w31 : w21;
    float* C  = g_wc[prod];
    float* bc = g_bc[prod];
    for (int idx = threadIdx.x; idx < 16 * F; idx += blockDim.x) {
        int k = rowg * 16 + (idx >> 7);
        int j = idx & 127;
        float s = 0.f;
        #pragma unroll 4
        for (int m = 0; m < F; m++) s += A[k * F + m] * B[m * F + j];
        C[k * F + j] = s;
    }
    if (rowg == 0 && threadIdx.x < F) {
        int j = threadIdx.x;
        float s = 0.f;
        #pragma unroll 4
        for (int m = 0; m < F; m++) s += bA[m] * B[m * F + j];
        bc[j] = s;
    }
}

// ---------------- weight prep: W[k][j] -> Wt_hi/lo[n=j][k], swizzled (split only)
__global__ void k_wprep(const float* __restrict__ w11) {
    const float* W = (blockIdx.x == 0) ? w11 : g_wc[blockIdx.x - 1];
    __nv_bfloat16* dhi = &g_wp[blockIdx.x][0][0];
    __nv_bfloat16* dlo = &g_wp[blockIdx.x][1][0];
    for (int idx = threadIdx.x; idx < F * F; idx += blockDim.x) {
        int n = idx >> 7, k = idx & 127;
        float v = W[k * F + n];
        __nv_bfloat16 h = __float2bfloat16(v);
        float l = v - __bfloat162float(h);
        int e = swz(n, k >> 1) * 2 + (k & 1);
        dhi[e] = h;
        dlo[e] = __float2bfloat16(l);
    }
}

// ---------------- tensor-core GEMM: H = relu(t @ W + bias), tile 64x128 ---------
// (round-11 structure: warp = 16 rows x 128 cols) ; H stored fp16.
// bias[col] = bias1[col] + (1+deg_row)*g_bc[bc_sel-1][col]  (bc_sel=0: none)
// dot_mode: outS[n] = H[n,:].w32 + b32 ; else g_m[n,:] = H[n,:] (fp16)
#define SM_TOT (2 * TM * F * 2 + 2 * F * F * 2 + 3 * F * 4)
__global__ void __launch_bounds__(128, 2)
k_gemm_mma(int slot, const float* __restrict__ bias1, int bc_sel, int dot_mode,
           const float* __restrict__ w32, const float* __restrict__ b32,
           float* __restrict__ outS) {
    extern __shared__ __align__(16) char smem[];
    __nv_bfloat16* sAhi = (__nv_bfloat16*)smem;            // 16 KB
    __nv_bfloat16* sAlo = sAhi + TM * F;                   // 16 KB
    __nv_bfloat16* sBhi = sAlo + TM * F;                   // 64 KB (hi then lo)
    float* sBias1 = (float*)(sBhi + 2 * F * F);
    float* sBiasC = sBias1 + F;
    float* sW32   = sBiasC + F;

    __half* out = (__half*)g_m;

    int tid = threadIdx.x;
    int lane = tid & 31, wid = tid >> 5;
    int nbase = blockIdx.x * TM;

    // ---- B (Wt hi+lo, pre-swizzled): linear 64 KB cp.async ----
    unsigned sB = s2u(sBhi);
    const char* gb = (const char*)&g_wp[slot][0][0];
    #pragma unroll
    for (int i = 0; i < 32; i++)
        cp16(sB + (tid + i * 128) * 16, gb + (size_t)(tid + i * 128) * 16);
    // ---- A (pre-split, pre-swizzled): linear 2 x 16 KB cp.async ----
    unsigned sAh = s2u(sAhi);
    unsigned sAl = s2u(sAlo);
    const char* gah = (const char*)(g_thi + (size_t)nbase * 64);
    const char* gal = (const char*)(g_tlo + (size_t)nbase * 64);
    #pragma unroll
    for (int i = 0; i < 8; i++) {
        cp16(sAh + (tid + i * 128) * 16, gah + (size_t)(tid + i * 128) * 16);
        cp16(sAl + (tid + i * 128) * 16, gal + (size_t)(tid + i * 128) * 16);
    }
    cp_commit();
    if (tid < F) {
        sBias1[tid] = bias1[tid];
        sBiasC[tid] = bc_sel ? g_bc[bc_sel - 1][tid] : 0.f;
        sW32[tid]   = dot_mode ? w32[tid] : 0.f;
    }
    cp_wait0();
    __syncthreads();

    const unsigned* uAhi = (const unsigned*)sAhi;
    const unsigned* uAlo = (const unsigned*)sAlo;
    const unsigned* uBhi = (const unsigned*)sBhi;
    const unsigned* uBlo = uBhi + F * F / 2;

    float acc[16][4];
    #pragma unroll
    for (int i = 0; i < 16; i++)
        #pragma unroll
        for (int j = 0; j < 4; j++) acc[i][j] = 0.f;

    int g = lane >> 2;        // group id 0..7
    int t = lane & 3;         // thread in group
    int m0 = wid * 16 + g;    // fragment row (lower 8), 0..63

    #pragma unroll
    for (int s = 0; s < 8; s++) {
        int w0 = 8 * s + t, w1 = w0 + 4;
        unsigned ahi[4], alo[4];
        ahi[0] = uAhi[swz(m0, w0)];     ahi[1] = uAhi[swz(m0 + 8, w0)];
        ahi[2] = uAhi[swz(m0, w1)];     ahi[3] = uAhi[swz(m0 + 8, w1)];
        alo[0] = uAlo[swz(m0, w0)];     alo[1] = uAlo[swz(m0 + 8, w0)];
        alo[2] = uAlo[swz(m0, w1)];     alo[3] = uAlo[swz(m0 + 8, w1)];
        #pragma unroll
        for (int nt = 0; nt < 16; nt++) {
            int n0 = nt * 8 + g;
            unsigned bh[2], bl[2];
            bh[0] = uBhi[swz(n0, w0)];  bh[1] = uBhi[swz(n0, w1)];
            bl[0] = uBlo[swz(n0, w0)];  bl[1] = uBlo[swz(n0, w1)];
            mma16816(acc[nt], ahi, bh);
            mma16816(acc[nt], ahi, bl);
            mma16816(acc[nt], alo, bh);
        }
    }

    // ---- epilogue ----
    int node0 = nbase + m0;
    int node1 = node0 + 8;
    float sc0 = 0.f, sc1 = 0.f;
    if (bc_sel) {
        if (node0 < N_NODES) sc0 = 1.f + (float)(g_off[node0 + 1] - g_off[node0]);
        if (node1 < N_NODES) sc1 = 1.f + (float)(g_off[node1 + 1] - g_off[node1]);
    }
    if (!dot_mode) {
        #pragma unroll
        for (int nt = 0; nt < 16; nt++) {
            int col = nt * 8 + 2 * t;
            float bx = sBias1[col], by = sBias1[col + 1];
            float cx = sBiasC[col], cy = sBiasC[col + 1];
            float o0x = fmaxf(acc[nt][0] + bx + sc0 * cx, 0.f);
            float o0y = fmaxf(acc[nt][1] + by + sc0 * cy, 0.f);
            float o1x = fmaxf(acc[nt][2] + bx + sc1 * cx, 0.f);
            float o1y = fmaxf(acc[nt][3] + by + sc1 * cy, 0.f);
            if (node0 < N_NODES)
                *(__half2*)(out + (size_t)node0 * F + col) = __floats2half2_rn(o0x, o0y);
            if (node1 < N_NODES)
                *(__half2*)(out + (size_t)node1 * F + col) = __floats2half2_rn(o1x, o1y);
        }
    } else {
        float p0 = 0.f, p1 = 0.f;
        #pragma unroll
        for (int nt = 0; nt < 16; nt++) {
            int col = nt * 8 + 2 * t;
            float bx = sBias1[col], by = sBias1[col + 1];
            float cx = sBiasC[col], cy = sBiasC[col + 1];
            p0 += fmaxf(acc[nt][0] + bx + sc0 * cx, 0.f) * sW32[col]
                + fmaxf(acc[nt][1] + by + sc0 * cy, 0.f) * sW32[col + 1];
            p1 += fmaxf(acc[nt][2] + bx + sc1 * cx, 0.f) * sW32[col]
                + fmaxf(acc[nt][3] + by + sc1 * cy, 0.f) * sW32[col + 1];
        }
        p0 += __shfl_xor_sync(0xffffffffu, p0, 1);
        p0 += __shfl_xor_sync(0xffffffffu, p0, 2);
        p1 += __shfl_xor_sync(0xffffffffu, p1, 1);
        p1 += __shfl_xor_sync(0xffffffffu, p1, 2);
        if (t == 0) {
            float bb = b32[0];
            if (node0 < N_NODES) outS[node0] = p0 + bb;
            if (node1 < N_NODES) outS[node1] = p1 + bb;
        }
    }
}

// ---------------- launch ---------------------------------------------------------
extern "C" void kernel_launch(void* const* d_in, const int* in_sizes, int n_in,
                              void* d_out, int out_size) {
    const float* x = (const float*)d_in[0];
    const void* ei = d_in[1];
    const float* w11 = (const float*)d_in[2];
    const float* b11 = (const float*)d_in[3];
    const float* w12 = (const float*)d_in[4];
    const float* b12 = (const float*)d_in[5];
    const float* w21 = (const float*)d_in[6];
    const float* b21 = (const float*)d_in[7];
    const float* w22 = (const float*)d_in[8];
    const float* b22 = (const float*)d_in[9];
    const float* w31 = (const float*)d_in[10];
    const float* b31 = (const float*)d_in[11];
    const float* w32 = (const float*)d_in[12];
    const float* b32 = (const float*)d_in[13];
    float* out = (float*)d_out;

    static int smem_set = 0;
    if (!smem_set) {
        cudaFuncSetAttribute(k_gemm_mma, cudaFuncAttributeMaxDynamicSharedMemorySize,
                             SM_TOT);
        smem_set = 1;
    }

    const int AGG_BLOCKS = (N_NODES * 32 + 255) / 256;   // warp per node

    k_count<<<N_EDGES / 256, 256>>>(ei);      // 1 (also zeroes lookback state)
    k_scan_lb<<<SCAN_B, 512>>>();             // 2
    k_fill<<<N_EDGES / 256, 256>>>(ei);       // 3
    k_agg<<<AGG_BLOCKS, 256>>>(x, 0);         // 4
    k_wcombine<<<16, 256>>>(w12, b12, w21, w22, b22, w31);  // 5
    k_wprep<<<3, 256>>>(w11);                 // 6

    // H1 = relu(agg(x)@W11 + b11)   (H stored fp16)
    k_gemm_mma<<<GEMM_BLOCKS, 128, SM_TOT>>>(0, b11, 0, 0, w32, b32, out);
    // H2 = relu(agg(H1)@Wc2 + (1+deg)bc2 + b21)
    k_agg<<<AGG_BLOCKS, 256>>>(x, 1);
    k_gemm_mma<<<GEMM_BLOCKS, 128, SM_TOT>>>(1, b21, 1, 0, w32, b32, out);
    // out = relu(agg(H2)@Wc3 + (1+deg)bc3 + b31) . w32 + b32
    k_agg<<<AGG_BLOCKS, 256>>>(x, 2);
    k_gemm_mma<<<GEMM_BLOCKS, 128, SM_TOT>>>(2, b31, 2, 1, w32, b32, out);
}

// round 14
// speedup vs baseline: 1.1096x; 1.0485x over previous
#include <cuda_runtime.h>
#include <cuda_bf16.h>
#include <cuda_fp16.h>
#include <cstdint>

#define N_NODES 100000
#define N_EDGES 1600000
#define F 128
#define SCAN_B 196      // ceil(100001 / 512)
#define TM 64
#define GEMM_BLOCKS ((N_NODES + TM - 1) / TM)   // 1563
#define N_PAD (GEMM_BLOCKS * TM)                // 100032 (tail rows stay zero)

// ---------------- scratch (static device globals; no cudaMalloc) ------------
__device__ __align__(16) int g_cnt[N_NODES + 1];   // zero-init; scan re-zeroes
__device__ __align__(16) int g_off[N_NODES + 1];
__device__ __align__(16) int g_cur[N_NODES];
__device__ __align__(16) int g_csr[N_EDGES];
__device__ __align__(16) unsigned long long g_desc[SCAN_B];  // lookback state
// agg output, pre-split bf16 hi/lo, pre-swizzled in GEMM smem layout
__device__ __align__(16) unsigned g_thi[(size_t)N_PAD * 64];
__device__ __align__(16) unsigned g_tlo[(size_t)N_PAD * 64];
__device__ __align__(16) __half g_x16[(size_t)N_NODES * F]; // x cast to fp16
__device__ __align__(16) __half g_m[(size_t)N_NODES * F];   // relu(H), fp16
__device__ __align__(16) float g_wc[2][F * F];           // W12@W21, W22@W31 (fp32)
__device__ __align__(16) float g_bc[2][F];               // b12@W21, b22@W31
// pre-split, transposed (Wt[n][k]), XOR-swizzled weights: [slot][hi/lo][128*128]
__device__ __align__(16) __nv_bfloat16 g_wp[3][2][F * F];

// ---------------- helpers -------------------------------------------------------
__device__ __forceinline__ unsigned pkbf2(float lo, float hi) {
    unsigned r;
    asm("cvt.rn.bf16x2.f32 %0, %1, %2;" : "=r"(r) : "f"(hi), "f"(lo));
    return r;
}
__device__ __forceinline__ unsigned s2u(const void* p) {
    unsigned a;
    asm("{ .reg .u64 t; cvta.to.shared.u64 t, %1; cvt.u32.u64 %0, t; }"
        : "=r"(a) : "l"(p));
    return a;
}
__device__ __forceinline__ void cp16(unsigned smem_addr, const void* gptr) {
    asm volatile("cp.async.cg.shared.global [%0], [%1], 16;" ::
                 "r"(smem_addr), "l"(gptr));
}
__device__ __forceinline__ void cp_commit() { asm volatile("cp.async.commit_group;"); }
__device__ __forceinline__ void cp_wait0()  { asm volatile("cp.async.wait_group 0;"); }

__device__ __forceinline__ void mma16816(float* d, const unsigned* a,
                                         const unsigned* b) {
    asm("mma.sync.aligned.m16n8k16.row.col.f32.bf16.bf16.f32 "
        "{%0,%1,%2,%3}, {%4,%5,%6,%7}, {%8,%9}, {%0,%1,%2,%3};"
        : "+f"(d[0]), "+f"(d[1]), "+f"(d[2]), "+f"(d[3])
        : "r"(a[0]), "r"(a[1]), "r"(a[2]), "r"(a[3]), "r"(b[0]), "r"(b[1]));
}

// swizzled 32-bit word index within a 128-col bf16 row (64 words/row)
__device__ __forceinline__ int swz(int row, int w) {
    return row * 64 + (w ^ ((row & 7) << 2));
}

__device__ __forceinline__ float4 up4(uint2 u) {
    __half2 a = *(__half2*)&u.x, b = *(__half2*)&u.y;
    float2 fa = __half22float2(a), fb = __half22float2(b);
    return make_float4(fa.x, fa.y, fb.x, fb.y);
}

// ---------------- edge dtype: block-local detection ---------------------------
__device__ __forceinline__ int block_is64(const void* ei, int e) {
    unsigned hw = ((const unsigned*)ei)[2 * e + 1];
    int any = __syncthreads_or(hw != 0u);
    return any ? 0 : 1;
}

// ---------------- x -> fp16 cast -------------------------------------------------
__global__ void k_xcast(const float* __restrict__ x) {
    int i = blockIdx.x * 256 + threadIdx.x;      // one float4 per thread
    if (i < N_NODES * (F / 4)) {
        float4 v = ((const float4*)x)[i];
        uint2 h;
        __half2 h0 = __floats2half2_rn(v.x, v.y);
        __half2 h1 = __floats2half2_rn(v.z, v.w);
        h.x = *(unsigned*)&h0;
        h.y = *(unsigned*)&h1;
        ((uint2*)g_x16)[i] = h;
    }
}

// ---------------- CSR build ----------------------------------------------------
__global__ void k_count(const void* __restrict__ ei) {
    if (blockIdx.x == 0 && threadIdx.x < SCAN_B) g_desc[threadIdx.x] = 0ULL;
    int e = blockIdx.x * 256 + threadIdx.x;
    int is64 = block_is64(ei, e);
    int d = is64 ? (int)(((const long long*)ei)[N_EDGES + e])
                 : ((const int*)ei)[N_EDGES + e];
    atomicAdd(&g_cnt[d + 1], 1);
}

// single-kernel decoupled-lookback scan over g_cnt[0..N_NODES] -> g_off, g_cur
__global__ void k_scan_lb() {
    __shared__ int wsum[16];
    __shared__ int s_exc;
    int tid = threadIdx.x, b = blockIdx.x;
    int i = b * 512 + tid;
    int lane = tid & 31, w = tid >> 5;
    int v = (i <= N_NODES) ? g_cnt[i] : 0;
    if (i <= N_NODES) g_cnt[i] = 0;                   // restore invariant
    int s = v;
    #pragma unroll
    for (int o = 1; o < 32; o <<= 1) {
        int t = __shfl_up_sync(0xffffffffu, s, o);
        if (lane >= o) s += t;
    }
    if (lane == 31) wsum[w] = s;
    __syncthreads();
    if (w == 0) {
        int ws = (lane < 16) ? wsum[lane] : 0;
        #pragma unroll
        for (int o = 1; o < 16; o <<= 1) {
            int t = __shfl_up_sync(0xffffffffu, ws, o);
            if (lane >= o) ws += t;
        }
        if (lane < 16) wsum[lane] = ws;
    }
    __syncthreads();
    int incl = s + (w > 0 ? wsum[w - 1] : 0);
    int total = wsum[15];
    if (tid == 0) {
        unsigned long long pub =
            ((unsigned long long)(b == 0 ? 2u : 1u) << 32) | (unsigned)total;
        atomicExch(&g_desc[b], pub);
    }
    int exc = 0;
    if (b > 0) {
        if (tid == 0) {
            int p = b - 1, run = 0;
            while (true) {
                unsigned long long d = atomicAdd(&g_desc[p], 0ULL);
                unsigned f = (unsigned)(d >> 32);
                if (f == 0u) continue;
                run += (int)(d & 0xffffffffu);
                if (f == 2u) break;
                p--;
            }
            s_exc = run;
            atomicExch(&g_desc[b], (2ULL << 32) | (unsigned)(run + total));
        }
        __syncthreads();
        exc = s_exc;
    }
    if (i <= N_NODES) {
        int val = exc + incl;
        g_off[i] = val;
        if (i < N_NODES) g_cur[i] = val;
    }
}

__global__ void k_fill(const void* __restrict__ ei) {
    int e = blockIdx.x * 256 + threadIdx.x;
    int is64 = block_is64(ei, e);
    int s, d;
    if (is64) {
        s = (int)(((const long long*)ei)[e]);
        d = (int)(((const long long*)ei)[N_EDGES + e]);
    } else {
        s = ((const int*)ei)[e];
        d = ((const int*)ei)[N_EDGES + e];
    }
    int p = atomicAdd(&g_cur[d], 1);
    g_csr[p] = s;
}

// ---------------- aggregation + split: t = in[i] + sum nbrs; store bf16 hi/lo ---
// All layers gather fp16 (layer 0: g_x16; layers 1,2: g_m).
// Output layout matches GEMM smem exactly: row node, word (2l)^((node&7)<<2).
__global__ void k_agg(int layer) {
    int w = (blockIdx.x * blockDim.x + threadIdx.x) >> 5;
    if (w >= N_NODES) return;
    int lane = threadIdx.x & 31;
    const uint2* hin = (layer == 0) ? (const uint2*)g_x16 : (const uint2*)g_m;
    float4 acc = up4(hin[(size_t)w * 32 + lane]);
    int e = g_off[w];
    int end = g_off[w + 1];
    for (; e + 4 <= end; e += 4) {
        int s0 = g_csr[e], s1 = g_csr[e + 1], s2 = g_csr[e + 2], s3 = g_csr[e + 3];
        float4 v0 = up4(hin[(size_t)s0 * 32 + lane]);
        float4 v1 = up4(hin[(size_t)s1 * 32 + lane]);
        float4 v2 = up4(hin[(size_t)s2 * 32 + lane]);
        float4 v3 = up4(hin[(size_t)s3 * 32 + lane]);
        acc.x += (v0.x + v1.x) + (v2.x + v3.x);
        acc.y += (v0.y + v1.y) + (v2.y + v3.y);
        acc.z += (v0.z + v1.z) + (v2.z + v3.z);
        acc.w += (v0.w + v1.w) + (v2.w + v3.w);
    }
    for (; e < end; e++) {
        int s0 = g_csr[e];
        float4 v0 = up4(hin[(size_t)s0 * 32 + lane]);
        acc.x += v0.x; acc.y += v0.y; acc.z += v0.z; acc.w += v0.w;
    }
    // split to bf16 hi/lo and store pre-swizzled
    __nv_bfloat16 bx = __float2bfloat16(acc.x);
    __nv_bfloat16 by = __float2bfloat16(acc.y);
    __nv_bfloat16 bz = __float2bfloat16(acc.z);
    __nv_bfloat16 bw = __float2bfloat16(acc.w);
    uint2 HI, LO;
    HI.x = ((unsigned)__bfloat16_as_ushort(by) << 16) | __bfloat16_as_ushort(bx);
    HI.y = ((unsigned)__bfloat16_as_ushort(bw) << 16) | __bfloat16_as_ushort(bz);
    LO.x = pkbf2(acc.x - __bfloat162float(bx), acc.y - __bfloat162float(by));
    LO.y = pkbf2(acc.z - __bfloat162float(bz), acc.w - __bfloat162float(bw));
    int wordp = (2 * lane) ^ ((w & 7) << 2);
    *(uint2*)(g_thi + (size_t)w * 64 + wordp) = HI;
    *(uint2*)(g_tlo + (size_t)w * 64 + wordp) = LO;
}

// ---------------- combined weights: Wc = A@B (fp32), bc = bA@B ------------------
__global__ void k_wcombine(const float* __restrict__ w12, const float* __restrict__ b12,
                           const float* __restrict__ w21, const float* __restrict__ w22,
                           const float* __restrict__ b22, const float* __restrict__ w31) {
    int prod = blockIdx.x >> 3, rowg = blockIdx.x & 7;
    const float* A  = prod ? w22 : w12;
    const float* bA = prod ? b22 : b12;
    const float* B  = prod ? w31 : w21;
    float* C  = g_wc[prod];
    float* bc = g_bc[prod];
    for (int idx = threadIdx.x; idx < 16 * F; idx += blockDim.x) {
        int k = rowg * 16 + (idx >> 7);
        int j = idx & 127;
        float s = 0.f;
        #pragma unroll 4
        for (int m = 0; m < F; m++) s += A[k * F + m] * B[m * F + j];
        C[k * F + j] = s;
    }
    if (rowg == 0 && threadIdx.x < F) {
        int j = threadIdx.x;
        float s = 0.f;
        #pragma unroll 4
        for (int m = 0; m < F; m++) s += bA[m] * B[m * F + j];
        bc[j] = s;
    }
}

// ---------------- weight prep: W[k][j] -> Wt_hi/lo[n=j][k], swizzled (split only)
__global__ void k_wprep(const float* __restrict__ w11) {
    const float* W = (blockIdx.x == 0) ? w11 : g_wc[blockIdx.x - 1];
    __nv_bfloat16* dhi = &g_wp[blockIdx.x][0][0];
    __nv_bfloat16* dlo = &g_wp[blockIdx.x][1][0];
    for (int idx = threadIdx.x; idx < F * F; idx += blockDim.x) {
        int n = idx >> 7, k = idx & 127;
        float v = W[k * F + n];
        __nv_bfloat16 h = __float2bfloat16(v);
        float l = v - __bfloat162float(h);
        int e = swz(n, k >> 1) * 2 + (k & 1);
        dhi[e] = h;
        dlo[e] = __float2bfloat16(l);
    }
}

// ---------------- tensor-core GEMM: H = relu(t @ W + bias), tile 64x128 ---------
// bias[col] = bias1[col] + (1+deg_row)*g_bc[bc_sel-1][col]  (bc_sel=0: none)
// dot_mode: outS[n] = H[n,:].w32 + b32 ; else g_m[n,:] = H[n,:] (fp16)
#define SM_TOT (2 * TM * F * 2 + 2 * F * F * 2 + 3 * F * 4)
__global__ void __launch_bounds__(128, 2)
k_gemm_mma(int slot, const float* __restrict__ bias1, int bc_sel, int dot_mode,
           const float* __restrict__ w32, const float* __restrict__ b32,
           float* __restrict__ outS) {
    extern __shared__ __align__(16) char smem[];
    __nv_bfloat16* sAhi = (__nv_bfloat16*)smem;            // 16 KB
    __nv_bfloat16* sAlo = sAhi + TM * F;                   // 16 KB
    __nv_bfloat16* sBhi = sAlo + TM * F;                   // 64 KB (hi then lo)
    float* sBias1 = (float*)(sBhi + 2 * F * F);
    float* sBiasC = sBias1 + F;
    float* sW32   = sBiasC + F;

    __half* out = (__half*)g_m;

    int tid = threadIdx.x;
    int lane = tid & 31, wid = tid >> 5;
    int nbase = blockIdx.x * TM;

    // ---- B (Wt hi+lo, pre-swizzled): linear 64 KB cp.async ----
    unsigned sB = s2u(sBhi);
    const char* gb = (const char*)&g_wp[slot][0][0];
    #pragma unroll
    for (int i = 0; i < 32; i++)
        cp16(sB + (tid + i * 128) * 16, gb + (size_t)(tid + i * 128) * 16);
    // ---- A (pre-split, pre-swizzled): linear 2 x 16 KB cp.async ----
    unsigned sAh = s2u(sAhi);
    unsigned sAl = s2u(sAlo);
    const char* gah = (const char*)(g_thi + (size_t)nbase * 64);
    const char* gal = (const char*)(g_tlo + (size_t)nbase * 64);
    #pragma unroll
    for (int i = 0; i < 8; i++) {
        cp16(sAh + (tid + i * 128) * 16, gah + (size_t)(tid + i * 128) * 16);
        cp16(sAl + (tid + i * 128) * 16, gal + (size_t)(tid + i * 128) * 16);
    }
    cp_commit();
    if (tid < F) {
        sBias1[tid] = bias1[tid];
        sBiasC[tid] = bc_sel ? g_bc[bc_sel - 1][tid] : 0.f;
        sW32[tid]   = dot_mode ? w32[tid] : 0.f;
    }
    cp_wait0();
    __syncthreads();

    const unsigned* uAhi = (const unsigned*)sAhi;
    const unsigned* uAlo = (const unsigned*)sAlo;
    const unsigned* uBhi = (const unsigned*)sBhi;
    const unsigned* uBlo = uBhi + F * F / 2;

    float acc[16][4];
    #pragma unroll
    for (int i = 0; i < 16; i++)
        #pragma unroll
        for (int j = 0; j < 4; j++) acc[i][j] = 0.f;

    int g = lane >> 2;        // group id 0..7
    int t = lane & 3;         // thread in group
    int m0 = wid * 16 + g;    // fragment row (lower 8), 0..63

    #pragma unroll
    for (int s = 0; s < 8; s++) {
        int w0 = 8 * s + t, w1 = w0 + 4;
        unsigned ahi[4], alo[4];
        ahi[0] = uAhi[swz(m0, w0)];     ahi[1] = uAhi[swz(m0 + 8, w0)];
        ahi[2] = uAhi[swz(m0, w1)];     ahi[3] = uAhi[swz(m0 + 8, w1)];
        alo[0] = uAlo[swz(m0, w0)];     alo[1] = uAlo[swz(m0 + 8, w0)];
        alo[2] = uAlo[swz(m0, w1)];     alo[3] = uAlo[swz(m0 + 8, w1)];
        #pragma unroll
        for (int nt = 0; nt < 16; nt++) {
            int n0 = nt * 8 + g;
            unsigned bh[2], bl[2];
            bh[0] = uBhi[swz(n0, w0)];  bh[1] = uBhi[swz(n0, w1)];
            bl[0] = uBlo[swz(n0, w0)];  bl[1] = uBlo[swz(n0, w1)];
            mma16816(acc[nt], ahi, bh);
            mma16816(acc[nt], ahi, bl);
            mma16816(acc[nt], alo, bh);
        }
    }

    // ---- epilogue ----
    int node0 = nbase + m0;
    int node1 = node0 + 8;
    float sc0 = 0.f, sc1 = 0.f;
    if (bc_sel) {
        if (node0 < N_NODES) sc0 = 1.f + (float)(g_off[node0 + 1] - g_off[node0]);
        if (node1 < N_NODES) sc1 = 1.f + (float)(g_off[node1 + 1] - g_off[node1]);
    }
    if (!dot_mode) {
        #pragma unroll
        for (int nt = 0; nt < 16; nt++) {
            int col = nt * 8 + 2 * t;
            float bx = sBias1[col], by = sBias1[col + 1];
            float cx = sBiasC[col], cy = sBiasC[col + 1];
            float o0x = fmaxf(acc[nt][0] + bx + sc0 * cx, 0.f);
            float o0y = fmaxf(acc[nt][1] + by + sc0 * cy, 0.f);
            float o1x = fmaxf(acc[nt][2] + bx + sc1 * cx, 0.f);
            float o1y = fmaxf(acc[nt][3] + by + sc1 * cy, 0.f);
            if (node0 < N_NODES)
                *(__half2*)(out + (size_t)node0 * F + col) = __floats2half2_rn(o0x, o0y);
            if (node1 < N_NODES)
                *(__half2*)(out + (size_t)node1 * F + col) = __floats2half2_rn(o1x, o1y);
        }
    } else {
        float p0 = 0.f, p1 = 0.f;
        #pragma unroll
        for (int nt = 0; nt < 16; nt++) {
            int col = nt * 8 + 2 * t;
            float bx = sBias1[col], by = sBias1[col + 1];
            float cx = sBiasC[col], cy = sBiasC[col + 1];
            p0 += fmaxf(acc[nt][0] + bx + sc0 * cx, 0.f) * sW32[col]
                + fmaxf(acc[nt][1] + by + sc0 * cy, 0.f) * sW32[col + 1];
            p1 += fmaxf(acc[nt][2] + bx + sc1 * cx, 0.f) * sW32[col]
                + fmaxf(acc[nt][3] + by + sc1 * cy, 0.f) * sW32[col + 1];
        }
        p0 += __shfl_xor_sync(0xffffffffu, p0, 1);
        p0 += __shfl_xor_sync(0xffffffffu, p0, 2);
        p1 += __shfl_xor_sync(0xffffffffu, p1, 1);
        p1 += __shfl_xor_sync(0xffffffffu, p1, 2);
        if (t == 0) {
            float bb = b32[0];
            if (node0 < N_NODES) outS[node0] = p0 + bb;
            if (node1 < N_NODES) outS[node1] = p1 + bb;
        }
    }
}

// ---------------- launch ---------------------------------------------------------
extern "C" void kernel_launch(void* const* d_in, const int* in_sizes, int n_in,
                              void* d_out, int out_size) {
    const float* x = (const float*)d_in[0];
    const void* ei = d_in[1];
    const float* w11 = (const float*)d_in[2];
    const float* b11 = (const float*)d_in[3];
    const float* w12 = (const float*)d_in[4];
    const float* b12 = (const float*)d_in[5];
    const float* w21 = (const float*)d_in[6];
    const float* b21 = (const float*)d_in[7];
    const float* w22 = (const float*)d_in[8];
    const float* b22 = (const float*)d_in[9];
    const float* w31 = (const float*)d_in[10];
    const float* b31 = (const float*)d_in[11];
    const float* w32 = (const float*)d_in[12];
    const float* b32 = (const float*)d_in[13];
    float* out = (float*)d_out;

    static int inited = 0;
    static cudaStream_t s_side;
    static cudaEvent_t ev_fork, ev_join;
    if (!inited) {
        cudaFuncSetAttribute(k_gemm_mma, cudaFuncAttributeMaxDynamicSharedMemorySize,
                             SM_TOT);
        cudaStreamCreateWithFlags(&s_side, cudaStreamNonBlocking);
        cudaEventCreateWithFlags(&ev_fork, cudaEventDisableTiming);
        cudaEventCreateWithFlags(&ev_join, cudaEventDisableTiming);
        inited = 1;
    }

    const int AGG_BLOCKS = (N_NODES * 32 + 255) / 256;   // warp per node

    // fork: x-cast + weight prep run concurrently with CSR build
    cudaEventRecord(ev_fork, 0);
    cudaStreamWaitEvent(s_side, ev_fork, 0);
    k_xcast<<<(N_NODES * 32 + 255) / 256, 256, 0, s_side>>>(x);
    k_wcombine<<<16, 256, 0, s_side>>>(w12, b12, w21, w22, b22, w31);
    k_wprep<<<3, 256, 0, s_side>>>(w11);
    cudaEventRecord(ev_join, s_side);

    // main: CSR build
    k_count<<<N_EDGES / 256, 256>>>(ei);
    k_scan_lb<<<SCAN_B, 512>>>();
    k_fill<<<N_EDGES / 256, 256>>>(ei);
    cudaStreamWaitEvent(0, ev_join, 0);

    // H1 = relu(agg(x)@W11 + b11)   (H stored fp16)
    k_agg<<<AGG_BLOCKS, 256>>>(0);
    k_gemm_mma<<<GEMM_BLOCKS, 128, SM_TOT>>>(0, b11, 0, 0, w32, b32, out);
    // H2 = relu(agg(H1)@Wc2 + (1+deg)bc2 + b21)
    k_agg<<<AGG_BLOCKS, 256>>>(1);
    k_gemm_mma<<<GEMM_BLOCKS, 128, SM_TOT>>>(1, b21, 1, 0, w32, b32, out);
    // out = relu(agg(H2)@Wc3 + (1+deg)bc3 + b31) . w32 + b32
    k_agg<<<AGG_BLOCKS, 256>>>(2);
    k_gemm_mma<<<GEMM_BLOCKS, 128, SM_TOT>>>(2, b31, 2, 1, w32, b32, out);
}

// round 15
// speedup vs baseline: 1.1199x; 1.0093x over previous
#include <cuda_runtime.h>
#include <cuda_bf16.h>
#include <cuda_fp16.h>
#include <cstdint>

#define N_NODES 100000
#define N_EDGES 1600000
#define F 128
#define SCAN_B 196      // ceil(100001 / 512)
#define TM 64
#define GEMM_BLOCKS ((N_NODES + TM - 1) / TM)   // 1563 tiles
#define GRID_P 296                               // persistent CTAs (2/SM)
#define N_PAD (GEMM_BLOCKS * TM)                // 100032 (tail rows stay zero)

// ---------------- scratch (static device globals; no cudaMalloc) ------------
__device__ __align__(16) int g_cnt[N_NODES + 1];   // zero-init; scan re-zeroes
__device__ __align__(16) int g_off[N_NODES + 1];
__device__ __align__(16) int g_cur[N_NODES];
__device__ __align__(16) int g_csr[N_EDGES];
__device__ __align__(16) unsigned long long g_desc[SCAN_B];  // lookback state
// agg output, pre-split bf16 hi/lo, pre-swizzled in GEMM smem layout
__device__ __align__(16) unsigned g_thi[(size_t)N_PAD * 64];
__device__ __align__(16) unsigned g_tlo[(size_t)N_PAD * 64];
__device__ __align__(16) __half g_x16[(size_t)N_NODES * F]; // x cast to fp16
__device__ __align__(16) __half g_m[(size_t)N_NODES * F];   // relu(H), fp16
__device__ __align__(16) float g_wc[2][F * F];           // W12@W21, W22@W31 (fp32)
__device__ __align__(16) float g_bc[2][F];               // b12@W21, b22@W31
// pre-split, transposed (Wt[n][k]), XOR-swizzled weights: [slot][hi/lo][128*128]
__device__ __align__(16) __nv_bfloat16 g_wp[3][2][F * F];

// ---------------- helpers -------------------------------------------------------
__device__ __forceinline__ unsigned pkbf2(float lo, float hi) {
    unsigned r;
    asm("cvt.rn.bf16x2.f32 %0, %1, %2;" : "=r"(r) : "f"(hi), "f"(lo));
    return r;
}
__device__ __forceinline__ unsigned s2u(const void* p) {
    unsigned a;
    asm("{ .reg .u64 t; cvta.to.shared.u64 t, %1; cvt.u32.u64 %0, t; }"
        : "=r"(a) : "l"(p));
    return a;
}
__device__ __forceinline__ void cp16(unsigned smem_addr, const void* gptr) {
    asm volatile("cp.async.cg.shared.global [%0], [%1], 16;" ::
                 "r"(smem_addr), "l"(gptr));
}
__device__ __forceinline__ void cp_commit() { asm volatile("cp.async.commit_group;"); }
__device__ __forceinline__ void cp_wait0()  { asm volatile("cp.async.wait_group 0;"); }

__device__ __forceinline__ void mma16816(float* d, const unsigned* a,
                                         const unsigned* b) {
    asm("mma.sync.aligned.m16n8k16.row.col.f32.bf16.bf16.f32 "
        "{%0,%1,%2,%3}, {%4,%5,%6,%7}, {%8,%9}, {%0,%1,%2,%3};"
        : "+f"(d[0]), "+f"(d[1]), "+f"(d[2]), "+f"(d[3])
        : "r"(a[0]), "r"(a[1]), "r"(a[2]), "r"(a[3]), "r"(b[0]), "r"(b[1]));
}

// swizzled 32-bit word index within a 128-col bf16 row (64 words/row)
__device__ __forceinline__ int swz(int row, int w) {
    return row * 64 + (w ^ ((row & 7) << 2));
}

__device__ __forceinline__ float4 up4(uint2 u) {
    __half2 a = *(__half2*)&u.x, b = *(__half2*)&u.y;
    float2 fa = __half22float2(a), fb = __half22float2(b);
    return make_float4(fa.x, fa.y, fb.x, fb.y);
}

// ---------------- edge dtype: block-local detection ---------------------------
__device__ __forceinline__ int block_is64(const void* ei, int e) {
    unsigned hw = ((const unsigned*)ei)[2 * e + 1];
    int any = __syncthreads_or(hw != 0u);
    return any ? 0 : 1;
}

// ---------------- x -> fp16 cast -------------------------------------------------
__global__ void k_xcast(const float* __restrict__ x) {
    int i = blockIdx.x * 256 + threadIdx.x;      // one float4 per thread
    if (i < N_NODES * (F / 4)) {
        float4 v = ((const float4*)x)[i];
        uint2 h;
        __half2 h0 = __floats2half2_rn(v.x, v.y);
        __half2 h1 = __floats2half2_rn(v.z, v.w);
        h.x = *(unsigned*)&h0;
        h.y = *(unsigned*)&h1;
        ((uint2*)g_x16)[i] = h;
    }
}

// ---------------- CSR build ----------------------------------------------------
__global__ void k_count(const void* __restrict__ ei) {
    if (blockIdx.x == 0 && threadIdx.x < SCAN_B) g_desc[threadIdx.x] = 0ULL;
    int e = blockIdx.x * 256 + threadIdx.x;
    int is64 = block_is64(ei, e);
    // values < 2^31: low 32-bit word suffices for int64 (LE)
    int d = ((const int*)ei)[is64 ? 2 * (N_EDGES + e) : (N_EDGES + e)];
    atomicAdd(&g_cnt[d + 1], 1);
}

// single-kernel decoupled-lookback scan over g_cnt[0..N_NODES] -> g_off, g_cur
__global__ void k_scan_lb() {
    __shared__ int wsum[16];
    __shared__ int s_exc;
    int tid = threadIdx.x, b = blockIdx.x;
    int i = b * 512 + tid;
    int lane = tid & 31, w = tid >> 5;
    int v = (i <= N_NODES) ? g_cnt[i] : 0;
    if (i <= N_NODES) g_cnt[i] = 0;                   // restore invariant
    int s = v;
    #pragma unroll
    for (int o = 1; o < 32; o <<= 1) {
        int t = __shfl_up_sync(0xffffffffu, s, o);
        if (lane >= o) s += t;
    }
    if (lane == 31) wsum[w] = s;
    __syncthreads();
    if (w == 0) {
        int ws = (lane < 16) ? wsum[lane] : 0;
        #pragma unroll
        for (int o = 1; o < 16; o <<= 1) {
            int t = __shfl_up_sync(0xffffffffu, ws, o);
            if (lane >= o) ws += t;
        }
        if (lane < 16) wsum[lane] = ws;
    }
    __syncthreads();
    int incl = s + (w > 0 ? wsum[w - 1] : 0);
    int total = wsum[15];
    if (tid == 0) {
        unsigned long long pub =
            ((unsigned long long)(b == 0 ? 2u : 1u) << 32) | (unsigned)total;
        atomicExch(&g_desc[b], pub);
    }
    int exc = 0;
    if (b > 0) {
        if (tid == 0) {
            int p = b - 1, run = 0;
            while (true) {
                unsigned long long d = atomicAdd(&g_desc[p], 0ULL);
                unsigned f = (unsigned)(d >> 32);
                if (f == 0u) continue;
                run += (int)(d & 0xffffffffu);
                if (f == 2u) break;
                p--;
            }
            s_exc = run;
            atomicExch(&g_desc[b], (2ULL << 32) | (unsigned)(run + total));
        }
        __syncthreads();
        exc = s_exc;
    }
    if (i <= N_NODES) {
        int val = exc + incl;
        g_off[i] = val;
        if (i < N_NODES) g_cur[i] = val;
    }
}

__global__ void k_fill(const void* __restrict__ ei) {
    int e = blockIdx.x * 256 + threadIdx.x;
    int is64 = block_is64(ei, e);
    const int* w = (const int*)ei;
    int s = w[is64 ? 2 * e : e];
    int d = w[is64 ? 2 * (N_EDGES + e) : (N_EDGES + e)];
    int p = atomicAdd(&g_cur[d], 1);
    g_csr[p] = s;
}

// ---------------- aggregation + split: t = in[i] + sum nbrs; store bf16 hi/lo ---
// All layers gather fp16 (layer 0: g_x16; layers 1,2: g_m).
// Output layout matches GEMM smem exactly: row node, word (2l)^((node&7)<<2).
__global__ void k_agg(int layer) {
    int w = (blockIdx.x * blockDim.x + threadIdx.x) >> 5;
    if (w >= N_NODES) return;
    int lane = threadIdx.x & 31;
    const uint2* hin = (layer == 0) ? (const uint2*)g_x16 : (const uint2*)g_m;
    float4 acc = up4(hin[(size_t)w * 32 + lane]);
    int e = g_off[w];
    int end = g_off[w + 1];
    for (; e + 4 <= end; e += 4) {
        int s0 = g_csr[e], s1 = g_csr[e + 1], s2 = g_csr[e + 2], s3 = g_csr[e + 3];
        float4 v0 = up4(hin[(size_t)s0 * 32 + lane]);
        float4 v1 = up4(hin[(size_t)s1 * 32 + lane]);
        float4 v2 = up4(hin[(size_t)s2 * 32 + lane]);
        float4 v3 = up4(hin[(size_t)s3 * 32 + lane]);
        acc.x += (v0.x + v1.x) + (v2.x + v3.x);
        acc.y += (v0.y + v1.y) + (v2.y + v3.y);
        acc.z += (v0.z + v1.z) + (v2.z + v3.z);
        acc.w += (v0.w + v1.w) + (v2.w + v3.w);
    }
    for (; e < end; e++) {
        int s0 = g_csr[e];
        float4 v0 = up4(hin[(size_t)s0 * 32 + lane]);
        acc.x += v0.x; acc.y += v0.y; acc.z += v0.z; acc.w += v0.w;
    }
    // split to bf16 hi/lo and store pre-swizzled
    __nv_bfloat16 bx = __float2bfloat16(acc.x);
    __nv_bfloat16 by = __float2bfloat16(acc.y);
    __nv_bfloat16 bz = __float2bfloat16(acc.z);
    __nv_bfloat16 bw = __float2bfloat16(acc.w);
    uint2 HI, LO;
    HI.x = ((unsigned)__bfloat16_as_ushort(by) << 16) | __bfloat16_as_ushort(bx);
    HI.y = ((unsigned)__bfloat16_as_ushort(bw) << 16) | __bfloat16_as_ushort(bz);
    LO.x = pkbf2(acc.x - __bfloat162float(bx), acc.y - __bfloat162float(by));
    LO.y = pkbf2(acc.z - __bfloat162float(bz), acc.w - __bfloat162float(bw));
    int wordp = (2 * lane) ^ ((w & 7) << 2);
    *(uint2*)(g_thi + (size_t)w * 64 + wordp) = HI;
    *(uint2*)(g_tlo + (size_t)w * 64 + wordp) = LO;
}

// ---------------- combined weights: Wc = A@B (fp32), bc = bA@B ------------------
__global__ void k_wcombine(const float* __restrict__ w12, const float* __restrict__ b12,
                           const float* __restrict__ w21, const float* __restrict__ w22,
                           const float* __restrict__ b22, const float* __restrict__ w31) {
    int prod = blockIdx.x >> 3, rowg = blockIdx.x & 7;
    const float* A  = prod ? w22 : w12;
    const float* bA = prod ? b22 : b12;
    const float* B  = prod ? w31 : w21;
    float* C  = g_wc[prod];
    float* bc = g_bc[prod];
    for (int idx = threadIdx.x; idx < 16 * F; idx += blockDim.x) {
        int k = rowg * 16 + (idx >> 7);
        int j = idx & 127;
        float s = 0.f;
        #pragma unroll 4
        for (int m = 0; m < F; m++) s += A[k * F + m] * B[m * F + j];
        C[k * F + j] = s;
    }
    if (rowg == 0 && threadIdx.x < F) {
        int j = threadIdx.x;
        float s = 0.f;
        #pragma unroll 4
        for (int m = 0; m < F; m++) s += bA[m] * B[m * F + j];
        bc[j] = s;
    }
}

// ---------------- weight prep: W[k][j] -> Wt_hi/lo[n=j][k], swizzled (split only)
__global__ void k_wprep(const float* __restrict__ w11) {
    const float* W = (blockIdx.x == 0) ? w11 : g_wc[blockIdx.x - 1];
    __nv_bfloat16* dhi = &g_wp[blockIdx.x][0][0];
    __nv_bfloat16* dlo = &g_wp[blockIdx.x][1][0];
    for (int idx = threadIdx.x; idx < F * F; idx += blockDim.x) {
        int n = idx >> 7, k = idx & 127;
        float v = W[k * F + n];
        __nv_bfloat16 h = __float2bfloat16(v);
        float l = v - __bfloat162float(h);
        int e = swz(n, k >> 1) * 2 + (k & 1);
        dhi[e] = h;
        dlo[e] = __float2bfloat16(l);
    }
}

// ---------------- persistent tensor-core GEMM: H = relu(t @ W + bias) -----------
// Grid = GRID_P CTAs, each loops tiles stride gridDim.x. B + biases loaded once;
// next tile's A cp.async overlaps the current epilogue.
// bias[col] = bias1[col] + (1+deg_row)*g_bc[bc_sel-1][col]  (bc_sel=0: none)
// dot_mode: outS[n] = H[n,:].w32 + b32 ; else g_m[n,:] = H[n,:] (fp16)
#define SM_TOT (2 * TM * F * 2 + 2 * F * F * 2 + 3 * F * 4)
__global__ void __launch_bounds__(128, 2)
k_gemm_mma(int slot, const float* __restrict__ bias1, int bc_sel, int dot_mode,
           const float* __restrict__ w32, const float* __restrict__ b32,
           float* __restrict__ outS) {
    extern __shared__ __align__(16) char smem[];
    __nv_bfloat16* sAhi = (__nv_bfloat16*)smem;            // 16 KB
    __nv_bfloat16* sAlo = sAhi + TM * F;                   // 16 KB
    __nv_bfloat16* sBhi = sAlo + TM * F;                   // 64 KB (hi then lo)
    float* sBias1 = (float*)(sBhi + 2 * F * F);
    float* sBiasC = sBias1 + F;
    float* sW32   = sBiasC + F;

    __half* out = (__half*)g_m;

    int tid = threadIdx.x;
    int lane = tid & 31, wid = tid >> 5;

    // ---- once: B (Wt hi+lo, pre-swizzled) + biases ----
    unsigned sB = s2u(sBhi);
    const char* gb = (const char*)&g_wp[slot][0][0];
    #pragma unroll
    for (int i = 0; i < 32; i++)
        cp16(sB + (tid + i * 128) * 16, gb + (size_t)(tid + i * 128) * 16);
    unsigned sAh = s2u(sAhi);
    unsigned sAl = s2u(sAlo);
    // first tile's A
    int tile = blockIdx.x;
    {
        const char* gah = (const char*)(g_thi + (size_t)tile * TM * 64);
        const char* gal = (const char*)(g_tlo + (size_t)tile * TM * 64);
        #pragma unroll
        for (int i = 0; i < 8; i++) {
            cp16(sAh + (tid + i * 128) * 16, gah + (size_t)(tid + i * 128) * 16);
            cp16(sAl + (tid + i * 128) * 16, gal + (size_t)(tid + i * 128) * 16);
        }
    }
    cp_commit();
    if (tid < F) {
        sBias1[tid] = bias1[tid];
        sBiasC[tid] = bc_sel ? g_bc[bc_sel - 1][tid] : 0.f;
        sW32[tid]   = dot_mode ? w32[tid] : 0.f;
    }
    cp_wait0();
    __syncthreads();

    const unsigned* uAhi = (const unsigned*)sAhi;
    const unsigned* uAlo = (const unsigned*)sAlo;
    const unsigned* uBhi = (const unsigned*)sBhi;
    const unsigned* uBlo = uBhi + F * F / 2;

    int g = lane >> 2;        // group id 0..7
    int t = lane & 3;         // thread in group
    int m0 = wid * 16 + g;    // fragment row (lower 8), 0..63
    float bb = dot_mode ? b32[0] : 0.f;

    while (tile < GEMM_BLOCKS) {
        int nbase = tile * TM;
        float acc[16][4];
        #pragma unroll
        for (int i = 0; i < 16; i++)
            #pragma unroll
            for (int j = 0; j < 4; j++) acc[i][j] = 0.f;

        #pragma unroll
        for (int s = 0; s < 8; s++) {
            int w0 = 8 * s + t, w1 = w0 + 4;
            unsigned ahi[4], alo[4];
            ahi[0] = uAhi[swz(m0, w0)];     ahi[1] = uAhi[swz(m0 + 8, w0)];
            ahi[2] = uAhi[swz(m0, w1)];     ahi[3] = uAhi[swz(m0 + 8, w1)];
            alo[0] = uAlo[swz(m0, w0)];     alo[1] = uAlo[swz(m0 + 8, w0)];
            alo[2] = uAlo[swz(m0, w1)];     alo[3] = uAlo[swz(m0 + 8, w1)];
            #pragma unroll
            for (int nt = 0; nt < 16; nt++) {
                int n0 = nt * 8 + g;
                unsigned bh[2], bl[2];
                bh[0] = uBhi[swz(n0, w0)];  bh[1] = uBhi[swz(n0, w1)];
                bl[0] = uBlo[swz(n0, w0)];  bl[1] = uBlo[swz(n0, w1)];
                mma16816(acc[nt], ahi, bh);
                mma16816(acc[nt], ahi, bl);
                mma16816(acc[nt], alo, bh);
            }
        }

        int next = tile + GRID_P;
        __syncthreads();                    // all warps done reading A smem
        if (next < GEMM_BLOCKS) {
            const char* gah = (const char*)(g_thi + (size_t)next * TM * 64);
            const char* gal = (const char*)(g_tlo + (size_t)next * TM * 64);
            #pragma unroll
            for (int i = 0; i < 8; i++) {
                cp16(sAh + (tid + i * 128) * 16, gah + (size_t)(tid + i * 128) * 16);
                cp16(sAl + (tid + i * 128) * 16, gal + (size_t)(tid + i * 128) * 16);
            }
            cp_commit();
        }

        // ---- epilogue (registers + persistent smem only) ----
        int node0 = nbase + m0;
        int node1 = node0 + 8;
        float sc0 = 0.f, sc1 = 0.f;
        if (bc_sel) {
            if (node0 < N_NODES) sc0 = 1.f + (float)(g_off[node0 + 1] - g_off[node0]);
            if (node1 < N_NODES) sc1 = 1.f + (float)(g_off[node1 + 1] - g_off[node1]);
        }
        if (!dot_mode) {
            #pragma unroll
            for (int nt = 0; nt < 16; nt++) {
                int col = nt * 8 + 2 * t;
                float bx = sBias1[col], by = sBias1[col + 1];
                float cx = sBiasC[col], cy = sBiasC[col + 1];
                float o0x = fmaxf(acc[nt][0] + bx + sc0 * cx, 0.f);
                float o0y = fmaxf(acc[nt][1] + by + sc0 * cy, 0.f);
                float o1x = fmaxf(acc[nt][2] + bx + sc1 * cx, 0.f);
                float o1y = fmaxf(acc[nt][3] + by + sc1 * cy, 0.f);
                if (node0 < N_NODES)
                    *(__half2*)(out + (size_t)node0 * F + col) = __floats2half2_rn(o0x, o0y);
                if (node1 < N_NODES)
                    *(__half2*)(out + (size_t)node1 * F + col) = __floats2half2_rn(o1x, o1y);
            }
        } else {
            float p0 = 0.f, p1 = 0.f;
            #pragma unroll
            for (int nt = 0; nt < 16; nt++) {
                int col = nt * 8 + 2 * t;
                float bx = sBias1[col], by = sBias1[col + 1];
                float cx = sBiasC[col], cy = sBiasC[col + 1];
                p0 += fmaxf(acc[nt][0] + bx + sc0 * cx, 0.f) * sW32[col]
                    + fmaxf(acc[nt][1] + by + sc0 * cy, 0.f) * sW32[col + 1];
                p1 += fmaxf(acc[nt][2] + bx + sc1 * cx, 0.f) * sW32[col]
                    + fmaxf(acc[nt][3] + by + sc1 * cy, 0.f) * sW32[col + 1];
            }
            p0 += __shfl_xor_sync(0xffffffffu, p0, 1);
            p0 += __shfl_xor_sync(0xffffffffu, p0, 2);
            p1 += __shfl_xor_sync(0xffffffffu, p1, 1);
            p1 += __shfl_xor_sync(0xffffffffu, p1, 2);
            if (t == 0) {
                if (node0 < N_NODES) outS[node0] = p0 + bb;
                if (node1 < N_NODES) outS[node1] = p1 + bb;
            }
        }

        cp_wait0();
        __syncthreads();                    // A(next) resident
        tile = next;
    }
}

// ---------------- launch ---------------------------------------------------------
extern "C" void kernel_launch(void* const* d_in, const int* in_sizes, int n_in,
                              void* d_out, int out_size) {
    const float* x = (const float*)d_in[0];
    const void* ei = d_in[1];
    const float* w11 = (const float*)d_in[2];
    const float* b11 = (const float*)d_in[3];
    const float* w12 = (const float*)d_in[4];
    const float* b12 = (const float*)d_in[5];
    const float* w21 = (const float*)d_in[6];
    const float* b21 = (const float*)d_in[7];
    const float* w22 = (const float*)d_in[8];
    const float* b22 = (const float*)d_in[9];
    const float* w31 = (const float*)d_in[10];
    const float* b31 = (const float*)d_in[11];
    const float* w32 = (const float*)d_in[12];
    const float* b32 = (const float*)d_in[13];
    float* out = (float*)d_out;

    static int inited = 0;
    static cudaStream_t s_side;
    static cudaEvent_t ev_fork, ev_join;
    if (!inited) {
        cudaFuncSetAttribute(k_gemm_mma, cudaFuncAttributeMaxDynamicSharedMemorySize,
                             SM_TOT);
        cudaStreamCreateWithFlags(&s_side, cudaStreamNonBlocking);
        cudaEventCreateWithFlags(&ev_fork, cudaEventDisableTiming);
        cudaEventCreateWithFlags(&ev_join, cudaEventDisableTiming);
        inited = 1;
    }

    const int AGG_BLOCKS = (N_NODES * 32 + 255) / 256;   // warp per node

    // fork: x-cast + weight prep run concurrently with CSR build
    cudaEventRecord(ev_fork, 0);
    cudaStreamWaitEvent(s_side, ev_fork, 0);
    k_xcast<<<(N_NODES * 32 + 255) / 256, 256, 0, s_side>>>(x);
    k_wcombine<<<16, 256, 0, s_side>>>(w12, b12, w21, w22, b22, w31);
    k_wprep<<<3, 256, 0, s_side>>>(w11);
    cudaEventRecord(ev_join, s_side);

    // main: CSR build
    k_count<<<N_EDGES / 256, 256>>>(ei);
    k_scan_lb<<<SCAN_B, 512>>>();
    k_fill<<<N_EDGES / 256, 256>>>(ei);
    cudaStreamWaitEvent(0, ev_join, 0);

    // H1 = relu(agg(x)@W11 + b11)   (H stored fp16)
    k_agg<<<AGG_BLOCKS, 256>>>(0);
    k_gemm_mma<<<GRID_P, 128, SM_TOT>>>(0, b11, 0, 0, w32, b32, out);
    // H2 = relu(agg(H1)@Wc2 + (1+deg)bc2 + b21)
    k_agg<<<AGG_BLOCKS, 256>>>(1);
    k_gemm_mma<<<GRID_P, 128, SM_TOT>>>(1, b21, 1, 0, w32, b32, out);
    // out = relu(agg(H2)@Wc3 + (1+deg)bc3 + b31) . w32 + b32
    k_agg<<<AGG_BLOCKS, 256>>>(2);
    k_gemm_mma<<<GRID_P, 128, SM_TOT>>>(2, b31, 2, 1, w32, b32, out);
}

// round 16
// speedup vs baseline: 1.2265x; 1.0952x over previous
#include <cuda_runtime.h>
#include <cuda_fp16.h>
#include <cstdint>

#define N_NODES 100000
#define N_EDGES 1600000
#define F 128
#define SCAN_B 196      // ceil(100001 / 512)
#define TM 64
#define GEMM_BLOCKS ((N_NODES + TM - 1) / TM)   // 1563 tiles
#define GRID_P 296                               // persistent CTAs (2/SM)
#define N_PAD (GEMM_BLOCKS * TM)                // 100032 (tail rows stay zero)

// ---------------- scratch (static device globals; no cudaMalloc) ------------
__device__ __align__(16) int g_cnt[N_NODES + 1];   // zero-init; scan re-zeroes
__device__ __align__(16) int g_off[N_NODES + 1];
__device__ __align__(16) int g_cur[N_NODES];
__device__ __align__(16) int g_csr[N_EDGES];
__device__ __align__(16) unsigned long long g_desc[SCAN_B];  // lookback state
// agg output, fp16, pre-swizzled in GEMM smem layout (64 words/row)
__device__ __align__(16) unsigned g_ta[(size_t)N_PAD * 64];
__device__ __align__(16) __half g_x16[(size_t)N_NODES * F]; // x cast to fp16
__device__ __align__(16) __half g_m[(size_t)N_NODES * F];   // relu(H), fp16
__device__ __align__(16) float g_wc[2][F * F];           // W12@W21, W22@W31 (fp32)
__device__ __align__(16) float g_bc[2][F];               // b12@W21, b22@W31
// fp16 hi/lo weights, transposed (Wt[n][k]), XOR-swizzled: [slot][hi/lo][128*128]
__device__ __align__(16) __half g_wp[3][2][F * F];

// ---------------- helpers -------------------------------------------------------
__device__ __forceinline__ unsigned s2u(const void* p) {
    unsigned a;
    asm("{ .reg .u64 t; cvta.to.shared.u64 t, %1; cvt.u32.u64 %0, t; }"
        : "=r"(a) : "l"(p));
    return a;
}
__device__ __forceinline__ void cp16(unsigned smem_addr, const void* gptr) {
    asm volatile("cp.async.cg.shared.global [%0], [%1], 16;" ::
                 "r"(smem_addr), "l"(gptr));
}
__device__ __forceinline__ void cp_commit() { asm volatile("cp.async.commit_group;"); }
__device__ __forceinline__ void cp_wait0()  { asm volatile("cp.async.wait_group 0;"); }

__device__ __forceinline__ void mma16816h(float* d, const unsigned* a,
                                          const unsigned* b) {
    asm("mma.sync.aligned.m16n8k16.row.col.f32.f16.f16.f32 "
        "{%0,%1,%2,%3}, {%4,%5,%6,%7}, {%8,%9}, {%0,%1,%2,%3};"
        : "+f"(d[0]), "+f"(d[1]), "+f"(d[2]), "+f"(d[3])
        : "r"(a[0]), "r"(a[1]), "r"(a[2]), "r"(a[3]), "r"(b[0]), "r"(b[1]));
}

// swizzled 32-bit word index within a 128-col fp16 row (64 words/row)
__device__ __forceinline__ int swz(int row, int w) {
    return row * 64 + (w ^ ((row & 7) << 2));
}

__device__ __forceinline__ float4 up4(uint2 u) {
    __half2 a = *(__half2*)&u.x, b = *(__half2*)&u.y;
    float2 fa = __half22float2(a), fb = __half22float2(b);
    return make_float4(fa.x, fa.y, fb.x, fb.y);
}

// ---------------- edge dtype: block-local detection ---------------------------
__device__ __forceinline__ int block_is64(const void* ei, int e) {
    unsigned hw = ((const unsigned*)ei)[2 * e + 1];
    int any = __syncthreads_or(hw != 0u);
    return any ? 0 : 1;
}

// ---------------- x -> fp16 cast -------------------------------------------------
__global__ void k_xcast(const float* __restrict__ x) {
    int i = blockIdx.x * 256 + threadIdx.x;      // one float4 per thread
    if (i < N_NODES * (F / 4)) {
        float4 v = ((const float4*)x)[i];
        uint2 h;
        __half2 h0 = __floats2half2_rn(v.x, v.y);
        __half2 h1 = __floats2half2_rn(v.z, v.w);
        h.x = *(unsigned*)&h0;
        h.y = *(unsigned*)&h1;
        ((uint2*)g_x16)[i] = h;
    }
}

// ---------------- CSR build ----------------------------------------------------
__global__ void k_count(const void* __restrict__ ei) {
    if (blockIdx.x == 0 && threadIdx.x < SCAN_B) g_desc[threadIdx.x] = 0ULL;
    int e = blockIdx.x * 256 + threadIdx.x;
    int is64 = block_is64(ei, e);
    int d = ((const int*)ei)[is64 ? 2 * (N_EDGES + e) : (N_EDGES + e)];
    atomicAdd(&g_cnt[d + 1], 1);
}

// single-kernel decoupled-lookback scan over g_cnt[0..N_NODES] -> g_off, g_cur
__global__ void k_scan_lb() {
    __shared__ int wsum[16];
    __shared__ int s_exc;
    int tid = threadIdx.x, b = blockIdx.x;
    int i = b * 512 + tid;
    int lane = tid & 31, w = tid >> 5;
    int v = (i <= N_NODES) ? g_cnt[i] : 0;
    if (i <= N_NODES) g_cnt[i] = 0;                   // restore invariant
    int s = v;
    #pragma unroll
    for (int o = 1; o < 32; o <<= 1) {
        int t = __shfl_up_sync(0xffffffffu, s, o);
        if (lane >= o) s += t;
    }
    if (lane == 31) wsum[w] = s;
    __syncthreads();
    if (w == 0) {
        int ws = (lane < 16) ? wsum[lane] : 0;
        #pragma unroll
        for (int o = 1; o < 16; o <<= 1) {
            int t = __shfl_up_sync(0xffffffffu, ws, o);
            if (lane >= o) ws += t;
        }
        if (lane < 16) wsum[lane] = ws;
    }
    __syncthreads();
    int incl = s + (w > 0 ? wsum[w - 1] : 0);
    int total = wsum[15];
    if (tid == 0) {
        unsigned long long pub =
            ((unsigned long long)(b == 0 ? 2u : 1u) << 32) | (unsigned)total;
        atomicExch(&g_desc[b], pub);
    }
    int exc = 0;
    if (b > 0) {
        if (tid == 0) {
            int p = b - 1, run = 0;
            while (true) {
                unsigned long long d = atomicAdd(&g_desc[p], 0ULL);
                unsigned f = (unsigned)(d >> 32);
                if (f == 0u) continue;
                run += (int)(d & 0xffffffffu);
                if (f == 2u) break;
                p--;
            }
            s_exc = run;
            atomicExch(&g_desc[b], (2ULL << 32) | (unsigned)(run + total));
        }
        __syncthreads();
        exc = s_exc;
    }
    if (i <= N_NODES) {
        int val = exc + incl;
        g_off[i] = val;
        if (i < N_NODES) g_cur[i] = val;
    }
}

__global__ void k_fill(const void* __restrict__ ei) {
    int e = blockIdx.x * 256 + threadIdx.x;
    int is64 = block_is64(ei, e);
    const int* w = (const int*)ei;
    int s = w[is64 ? 2 * e : e];
    int d = w[is64 ? 2 * (N_EDGES + e) : (N_EDGES + e)];
    int p = atomicAdd(&g_cur[d], 1);
    g_csr[p] = s;
}

// ---------------- aggregation: t = in[i] + sum nbrs; store fp16 swizzled --------
// All layers gather fp16 (layer 0: g_x16; layers 1,2: g_m).
__global__ void k_agg(int layer) {
    int w = (blockIdx.x * blockDim.x + threadIdx.x) >> 5;
    if (w >= N_NODES) return;
    int lane = threadIdx.x & 31;
    const uint2* hin = (layer == 0) ? (const uint2*)g_x16 : (const uint2*)g_m;
    float4 acc = up4(hin[(size_t)w * 32 + lane]);
    int e = g_off[w];
    int end = g_off[w + 1];
    for (; e + 4 <= end; e += 4) {
        int s0 = g_csr[e], s1 = g_csr[e + 1], s2 = g_csr[e + 2], s3 = g_csr[e + 3];
        float4 v0 = up4(hin[(size_t)s0 * 32 + lane]);
        float4 v1 = up4(hin[(size_t)s1 * 32 + lane]);
        float4 v2 = up4(hin[(size_t)s2 * 32 + lane]);
        float4 v3 = up4(hin[(size_t)s3 * 32 + lane]);
        acc.x += (v0.x + v1.x) + (v2.x + v3.x);
        acc.y += (v0.y + v1.y) + (v2.y + v3.y);
        acc.z += (v0.z + v1.z) + (v2.z + v3.z);
        acc.w += (v0.w + v1.w) + (v2.w + v3.w);
    }
    for (; e < end; e++) {
        int s0 = g_csr[e];
        float4 v0 = up4(hin[(size_t)s0 * 32 + lane]);
        acc.x += v0.x; acc.y += v0.y; acc.z += v0.z; acc.w += v0.w;
    }
    // fp16 pack, pre-swizzled store (one uint2 = 4 halves)
    __half2 h0 = __floats2half2_rn(acc.x, acc.y);
    __half2 h1 = __floats2half2_rn(acc.z, acc.w);
    uint2 HV;
    HV.x = *(unsigned*)&h0;
    HV.y = *(unsigned*)&h1;
    int wordp = (2 * lane) ^ ((w & 7) << 2);
    *(uint2*)(g_ta + (size_t)w * 64 + wordp) = HV;
}

// ---------------- combined weights: Wc = A@B (fp32), bc = bA@B ------------------
__global__ void k_wcombine(const float* __restrict__ w12, const float* __restrict__ b12,
                           const float* __restrict__ w21, const float* __restrict__ w22,
                           const float* __restrict__ b22, const float* __restrict__ w31) {
    int prod = blockIdx.x >> 3, rowg = blockIdx.x & 7;
    const float* A  = prod ? w22 : w12;
    const float* bA = prod ? b22 : b12;
    const float* B  = prod ? w31 : w21;
    float* C  = g_wc[prod];
    float* bc = g_bc[prod];
    for (int idx = threadIdx.x; idx < 16 * F; idx += blockDim.x) {
        int k = rowg * 16 + (idx >> 7);
        int j = idx & 127;
        float s = 0.f;
        #pragma unroll 4
        for (int m = 0; m < F; m++) s += A[k * F + m] * B[m * F + j];
        C[k * F + j] = s;
    }
    if (rowg == 0 && threadIdx.x < F) {
        int j = threadIdx.x;
        float s = 0.f;
        #pragma unroll 4
        for (int m = 0; m < F; m++) s += bA[m] * B[m * F + j];
        bc[j] = s;
    }
}

// ---------------- weight prep: W[k][j] -> fp16 Wt_hi/lo[n=j][k], swizzled -------
__global__ void k_wprep(const float* __restrict__ w11) {
    const float* W = (blockIdx.x == 0) ? w11 : g_wc[blockIdx.x - 1];
    __half* dhi = &g_wp[blockIdx.x][0][0];
    __half* dlo = &g_wp[blockIdx.x][1][0];
    for (int idx = threadIdx.x; idx < F * F; idx += blockDim.x) {
        int n = idx >> 7, k = idx & 127;
        float v = W[k * F + n];
        __half h = __float2half_rn(v);
        float l = v - __half2float(h);
        int e = swz(n, k >> 1) * 2 + (k & 1);
        dhi[e] = h;
        dlo[e] = __float2half_rn(l);
    }
}

// ---------------- persistent tensor-core GEMM: H = relu(t @ W + bias) -----------
// A: single fp16 (pre-swizzled g_ta). B: fp16 hi/lo. 2 MMA products per tile.
// bias[col] = bias1[col] + (1+deg_row)*g_bc[bc_sel-1][col]  (bc_sel=0: none)
// dot_mode: outS[n] = H[n,:].w32 + b32 ; else g_m[n,:] = H[n,:] (fp16)
#define SM_TOT (TM * F * 2 + 2 * F * F * 2 + 3 * F * 4)
__global__ void __launch_bounds__(128, 2)
k_gemm_mma(int slot, const float* __restrict__ bias1, int bc_sel, int dot_mode,
           const float* __restrict__ w32, const float* __restrict__ b32,
           float* __restrict__ outS) {
    extern __shared__ __align__(16) char smem[];
    __half* sA = (__half*)smem;                            // 16 KB
    __half* sBhi = sA + TM * F;                            // 64 KB (hi then lo)
    float* sBias1 = (float*)(sBhi + 2 * F * F);
    float* sBiasC = sBias1 + F;
    float* sW32   = sBiasC + F;

    __half* out = (__half*)g_m;

    int tid = threadIdx.x;
    int lane = tid & 31, wid = tid >> 5;

    // ---- once: B (fp16 hi+lo, pre-swizzled) + biases ----
    unsigned sB = s2u(sBhi);
    const char* gb = (const char*)&g_wp[slot][0][0];
    #pragma unroll
    for (int i = 0; i < 32; i++)
        cp16(sB + (tid + i * 128) * 16, gb + (size_t)(tid + i * 128) * 16);
    unsigned sAh = s2u(sA);
    // first tile's A
    int tile = blockIdx.x;
    {
        const char* ga = (const char*)(g_ta + (size_t)tile * TM * 64);
        #pragma unroll
        for (int i = 0; i < 8; i++)
            cp16(sAh + (tid + i * 128) * 16, ga + (size_t)(tid + i * 128) * 16);
    }
    cp_commit();
    if (tid < F) {
        sBias1[tid] = bias1[tid];
        sBiasC[tid] = bc_sel ? g_bc[bc_sel - 1][tid] : 0.f;
        sW32[tid]   = dot_mode ? w32[tid] : 0.f;
    }
    cp_wait0();
    __syncthreads();

    const unsigned* uA = (const unsigned*)sA;
    const unsigned* uBhi = (const unsigned*)sBhi;
    const unsigned* uBlo = uBhi + F * F / 2;

    int g = lane >> 2;        // group id 0..7
    int t = lane & 3;         // thread in group
    int m0 = wid * 16 + g;    // fragment row (lower 8), 0..63
    float bb = dot_mode ? b32[0] : 0.f;

    while (tile < GEMM_BLOCKS) {
        int nbase = tile * TM;
        float acc[16][4];
        #pragma unroll
        for (int i = 0; i < 16; i++)
            #pragma unroll
            for (int j = 0; j < 4; j++) acc[i][j] = 0.f;

        #pragma unroll
        for (int s = 0; s < 8; s++) {
            int w0 = 8 * s + t, w1 = w0 + 4;
            unsigned a[4];
            a[0] = uA[swz(m0, w0)];     a[1] = uA[swz(m0 + 8, w0)];
            a[2] = uA[swz(m0, w1)];     a[3] = uA[swz(m0 + 8, w1)];
            #pragma unroll
            for (int nt = 0; nt < 16; nt++) {
                int n0 = nt * 8 + g;
                unsigned bh[2], bl[2];
                bh[0] = uBhi[swz(n0, w0)];  bh[1] = uBhi[swz(n0, w1)];
                bl[0] = uBlo[swz(n0, w0)];  bl[1] = uBlo[swz(n0, w1)];
                mma16816h(acc[nt], a, bh);
                mma16816h(acc[nt], a, bl);
            }
        }

        int next = tile + GRID_P;
        __syncthreads();                    // all warps done reading A smem
        if (next < GEMM_BLOCKS) {
            const char* ga = (const char*)(g_ta + (size_t)next * TM * 64);
            #pragma unroll
            for (int i = 0; i < 8; i++)
                cp16(sAh + (tid + i * 128) * 16, ga + (size_t)(tid + i * 128) * 16);
            cp_commit();
        }

        // ---- epilogue (registers + persistent smem only) ----
        int node0 = nbase + m0;
        int node1 = node0 + 8;
        float sc0 = 0.f, sc1 = 0.f;
        if (bc_sel) {
            if (node0 < N_NODES) sc0 = 1.f + (float)(g_off[node0 + 1] - g_off[node0]);
            if (node1 < N_NODES) sc1 = 1.f + (float)(g_off[node1 + 1] - g_off[node1]);
        }
        if (!dot_mode) {
            #pragma unroll
            for (int nt = 0; nt < 16; nt++) {
                int col = nt * 8 + 2 * t;
                float bx = sBias1[col], by = sBias1[col + 1];
                float cx = sBiasC[col], cy = sBiasC[col + 1];
                float o0x = fmaxf(acc[nt][0] + bx + sc0 * cx, 0.f);
                float o0y = fmaxf(acc[nt][1] + by + sc0 * cy, 0.f);
                float o1x = fmaxf(acc[nt][2] + bx + sc1 * cx, 0.f);
                float o1y = fmaxf(acc[nt][3] + by + sc1 * cy, 0.f);
                if (node0 < N_NODES)
                    *(__half2*)(out + (size_t)node0 * F + col) = __floats2half2_rn(o0x, o0y);
                if (node1 < N_NODES)
                    *(__half2*)(out + (size_t)node1 * F + col) = __floats2half2_rn(o1x, o1y);
            }
        } else {
            float p0 = 0.f, p1 = 0.f;
            #pragma unroll
            for (int nt = 0; nt < 16; nt++) {
                int col = nt * 8 + 2 * t;
                float bx = sBias1[col], by = sBias1[col + 1];
                float cx = sBiasC[col], cy = sBiasC[col + 1];
                p0 += fmaxf(acc[nt][0] + bx + sc0 * cx, 0.f) * sW32[col]
                    + fmaxf(acc[nt][1] + by + sc0 * cy, 0.f) * sW32[col + 1];
                p1 += fmaxf(acc[nt][2] + bx + sc1 * cx, 0.f) * sW32[col]
                    + fmaxf(acc[nt][3] + by + sc1 * cy, 0.f) * sW32[col + 1];
            }
            p0 += __shfl_xor_sync(0xffffffffu, p0, 1);
            p0 += __shfl_xor_sync(0xffffffffu, p0, 2);
            p1 += __shfl_xor_sync(0xffffffffu, p1, 1);
            p1 += __shfl_xor_sync(0xffffffffu, p1, 2);
            if (t == 0) {
                if (node0 < N_NODES) outS[node0] = p0 + bb;
                if (node1 < N_NODES) outS[node1] = p1 + bb;
            }
        }

        cp_wait0();
        __syncthreads();                    // A(next) resident
        tile = next;
    }
}

// ---------------- launch ---------------------------------------------------------
extern "C" void kernel_launch(void* const* d_in, const int* in_sizes, int n_in,
                              void* d_out, int out_size) {
    const float* x = (const float*)d_in[0];
    const void* ei = d_in[1];
    const float* w11 = (const float*)d_in[2];
    const float* b11 = (const float*)d_in[3];
    const float* w12 = (const float*)d_in[4];
    const float* b12 = (const float*)d_in[5];
    const float* w21 = (const float*)d_in[6];
    const float* b21 = (const float*)d_in[7];
    const float* w22 = (const float*)d_in[8];
    const float* b22 = (const float*)d_in[9];
    const float* w31 = (const float*)d_in[10];
    const float* b31 = (const float*)d_in[11];
    const float* w32 = (const float*)d_in[12];
    const float* b32 = (const float*)d_in[13];
    float* out = (float*)d_out;

    static int inited = 0;
    static cudaStream_t s_side;
    static cudaEvent_t ev_fork, ev_join;
    if (!inited) {
        cudaFuncSetAttribute(k_gemm_mma, cudaFuncAttributeMaxDynamicSharedMemorySize,
                             SM_TOT);
        cudaStreamCreateWithFlags(&s_side, cudaStreamNonBlocking);
        cudaEventCreateWithFlags(&ev_fork, cudaEventDisableTiming);
        cudaEventCreateWithFlags(&ev_join, cudaEventDisableTiming);
        inited = 1;
    }

    const int AGG_BLOCKS = (N_NODES * 32 + 255) / 256;   // warp per node

    // fork: x-cast + weight prep run concurrently with CSR build
    cudaEventRecord(ev_fork, 0);
    cudaStreamWaitEvent(s_side, ev_fork, 0);
    k_xcast<<<(N_NODES * 32 + 255) / 256, 256, 0, s_side>>>(x);
    k_wcombine<<<16, 256, 0, s_side>>>(w12, b12, w21, w22, b22, w31);
    k_wprep<<<3, 256, 0, s_side>>>(w11);
    cudaEventRecord(ev_join, s_side);

    // main: CSR build
    k_count<<<N_EDGES / 256, 256>>>(ei);
    k_scan_lb<<<SCAN_B, 512>>>();
    k_fill<<<N_EDGES / 256, 256>>>(ei);
    cudaStreamWaitEvent(0, ev_join, 0);

    // H1 = relu(agg(x)@W11 + b11)   (H stored fp16)
    k_agg<<<AGG_BLOCKS, 256>>>(0);
    k_gemm_mma<<<GRID_P, 128, SM_TOT>>>(0, b11, 0, 0, w32, b32, out);
    // H2 = relu(agg(H1)@Wc2 + (1+deg)bc2 + b21)
    k_agg<<<AGG_BLOCKS, 256>>>(1);
    k_gemm_mma<<<GRID_P, 128, SM_TOT>>>(1, b21, 1, 0, w32, b32, out);
    // out = relu(agg(H2)@Wc3 + (1+deg)bc3 + b31) . w32 + b32
    k_agg<<<AGG_BLOCKS, 256>>>(2);
    k_gemm_mma<<<GRID_P, 128, SM_TOT>>>(2, b31, 2, 1, w32, b32, out);
}